// round 1
// baseline (speedup 1.0000x reference)
#include <cuda_runtime.h>
#include <math.h>

#define NN 30000
#define NE 480000
#define NB 4096

// ---------------- device scratch (no allocations allowed) ----------------
__device__ float g_x1[NN * 881];    // after bb_fc2 (+relu+softthr)
__device__ float g_x [NN * 256];    // ping
__device__ float g_h [NN * 256];    // pong
__device__ float g_hw[NN * 256];    // H @ W scratch
__device__ float g_dinv[NN];
__device__ int   g_deg[NN];
__device__ int   g_cnt[NN];
__device__ int   g_rowptr[NN + 1];
__device__ int   g_col[NE];
__device__ float g_wgt[NE];
__device__ float g_xc [NB * 1024];
__device__ float g_xc2[NB * 1024];

// ---------------- graph preprocessing ----------------
__global__ void k_zero_deg() {
    int i = blockIdx.x * blockDim.x + threadIdx.x;
    if (i < NN) { g_deg[i] = 0; g_cnt[i] = 0; }
}

// edges layout: [2, NE] row-major; src = edges[0..NE), dst = edges[NE..2NE)
__global__ void k_count(const int* __restrict__ edges) {
    int e = blockIdx.x * blockDim.x + threadIdx.x;
    if (e < NE) atomicAdd(&g_deg[edges[NE + e]], 1);
}

__global__ void k_dinv() {
    int i = blockIdx.x * blockDim.x + threadIdx.x;
    if (i < NN) g_dinv[i] = rsqrtf((float)(g_deg[i] + 1));  // +1 self loop
}

__global__ void k_scan() {
    __shared__ int part[1024];
    int tid = threadIdx.x;
    const int chunk = (NN + 1023) / 1024;  // 30
    int start = tid * chunk;
    int s = 0;
    for (int i = 0; i < chunk; i++) { int j = start + i; if (j < NN) s += g_deg[j]; }
    part[tid] = s;
    __syncthreads();
    for (int off = 1; off < 1024; off <<= 1) {
        int v = (tid >= off) ? part[tid - off] : 0;
        __syncthreads();
        part[tid] += v;
        __syncthreads();
    }
    int run = (tid > 0) ? part[tid - 1] : 0;
    for (int i = 0; i < chunk; i++) {
        int j = start + i;
        if (j < NN) { g_rowptr[j] = run; run += g_deg[j]; }
    }
    if (tid == 1023) g_rowptr[NN] = part[1023];
}

__global__ void k_fill(const int* __restrict__ edges) {
    int e = blockIdx.x * blockDim.x + threadIdx.x;
    if (e < NE) {
        int s = edges[e];
        int d = edges[NE + e];
        int pos = g_rowptr[d] + atomicAdd(&g_cnt[d], 1);
        g_col[pos] = s;
        g_wgt[pos] = g_dinv[s] * g_dinv[d];
    }
}

// ---------------- SGEMM: C[M,N] = A[M,K] @ B[K,N] (+bias, epilogue) --------
// EPI: 0 = none, 1 = relu, 2 = relu then soft-threshold (== max(z - thr, 0))
#define BM 128
#define BN 128
#define BK 16

template <int EPI>
__global__ __launch_bounds__(256) void k_sgemm(
    const float* __restrict__ A, const float* __restrict__ B,
    const float* __restrict__ bias, const float* __restrict__ thr_p,
    float* __restrict__ C, int M, int N, int K)
{
    __shared__ float As[BK][BM];
    __shared__ float Bs[BK][BN];
    int tid = threadIdx.x;
    int row0 = blockIdx.y * BM, col0 = blockIdx.x * BN;
    int tx = tid & 15, ty = tid >> 4;

    float acc[8][8];
#pragma unroll
    for (int i = 0; i < 8; i++)
#pragma unroll
        for (int j = 0; j < 8; j++) acc[i][j] = 0.f;

    for (int k0 = 0; k0 < K; k0 += BK) {
#pragma unroll
        for (int i = 0; i < 8; i++) {                 // A tile: BM x BK
            int idx = i * 256 + tid;
            int r = idx >> 4, c = idx & 15;
            int gr = row0 + r, gc = k0 + c;
            As[c][r] = (gr < M && gc < K) ? A[(long)gr * K + gc] : 0.f;
        }
#pragma unroll
        for (int i = 0; i < 8; i++) {                 // B tile: BK x BN
            int idx = i * 256 + tid;
            int r = idx >> 7, c = idx & 127;
            int gr = k0 + r, gc = col0 + c;
            Bs[r][c] = (gr < K && gc < N) ? B[(long)gr * N + gc] : 0.f;
        }
        __syncthreads();
#pragma unroll
        for (int kk = 0; kk < BK; kk++) {
            float ra[8], rb[8];
#pragma unroll
            for (int i = 0; i < 8; i++) ra[i] = As[kk][ty * 8 + i];
#pragma unroll
            for (int j = 0; j < 8; j++) rb[j] = Bs[kk][tx * 8 + j];
#pragma unroll
            for (int i = 0; i < 8; i++)
#pragma unroll
                for (int j = 0; j < 8; j++) acc[i][j] = fmaf(ra[i], rb[j], acc[i][j]);
        }
        __syncthreads();
    }

    float thr = (EPI == 2) ? thr_p[0] : 0.f;
#pragma unroll
    for (int i = 0; i < 8; i++) {
        int gr = row0 + ty * 8 + i;
        if (gr >= M) continue;
#pragma unroll
        for (int j = 0; j < 8; j++) {
            int gc = col0 + tx * 8 + j;
            if (gc >= N) continue;
            float v = acc[i][j] + (bias ? bias[gc] : 0.f);
            if (EPI == 1) v = fmaxf(v, 0.f);
            if (EPI == 2) { v = fmaxf(v, 0.f); v = fmaxf(v - thr, 0.f); }
            C[(long)gr * N + gc] = v;
        }
    }
}

// ---------------- GCN gather: out = elu(segment_sum(msg) + selfloop + bias) --
__global__ void k_gather(const float* __restrict__ hw, const float* __restrict__ bias,
                         float* __restrict__ out, int F)
{
    int n = blockIdx.x;
    int f = threadIdx.x;
    float d = g_dinv[n];
    float acc = d * d * hw[(long)n * F + f];       // self loop
    int s = g_rowptr[n], e = g_rowptr[n + 1];
    for (int i = s; i < e; i++)
        acc += g_wgt[i] * __ldg(&hw[(long)g_col[i] * F + f]);
    acc += bias[f];
    out[(long)n * F + f] = acc > 0.f ? acc : expm1f(acc);
}

// ---------------- pair readout: concat + L2 normalize ----------------
__global__ void k_pair(const float* __restrict__ h,
                       const int* __restrict__ i1, const int* __restrict__ i2,
                       float* __restrict__ xc)
{
    int p = blockIdx.x;
    int f = threadIdx.x;  // 256
    float v = (f < 128) ? h[(long)i1[p] * 128 + f] : h[(long)i2[p] * 128 + (f - 128)];
    __shared__ float red[256];
    red[f] = v * v;
    __syncthreads();
    for (int off = 128; off > 0; off >>= 1) {
        if (f < off) red[f] += red[f + off];
        __syncthreads();
    }
    float norm = fmaxf(sqrtf(red[0]), 1e-12f);
    xc[(long)p * 256 + f] = v / norm;
}

// ---------------- final 64->2 ----------------
__global__ void k_out(const float* __restrict__ x, const float* __restrict__ W,
                      const float* __restrict__ b, float* __restrict__ out)
{
    int idx = blockIdx.x * blockDim.x + threadIdx.x;
    if (idx >= NB * 2) return;
    int p = idx >> 1, c = idx & 1;
    float acc = b[c];
#pragma unroll
    for (int k = 0; k < 64; k++) acc += x[p * 64 + k] * W[k * 2 + c];
    out[idx] = acc;
}

// ---------------- launch ----------------
extern "C" void kernel_launch(void* const* d_in, const int* in_sizes, int n_in,
                              void* d_out, int out_size)
{
    const float* cid   = (const float*)d_in[0];
    const int*   edges = (const int*)  d_in[1];   // jax x64 disabled -> int32
    const int*   i1    = (const int*)  d_in[2];
    const int*   i2    = (const int*)  d_in[3];
    const float* thr   = (const float*)d_in[4];
    const float* bb2W  = (const float*)d_in[5];  const float* bb2b = (const float*)d_in[6];
    const float* bb3W  = (const float*)d_in[7];  const float* bb3b = (const float*)d_in[8];
    const float* g1W   = (const float*)d_in[9];  const float* g1b  = (const float*)d_in[10];
    const float* g2W   = (const float*)d_in[11]; const float* g2b  = (const float*)d_in[12];
    const float* g3W   = (const float*)d_in[13]; const float* g3b  = (const float*)d_in[14];
    const float* g4W   = (const float*)d_in[15]; const float* g4b  = (const float*)d_in[16];
    const float* g5W   = (const float*)d_in[17]; const float* g5b  = (const float*)d_in[18];
    const float* f1W   = (const float*)d_in[19]; const float* f1b  = (const float*)d_in[20];
    const float* f2W   = (const float*)d_in[21]; const float* f2b  = (const float*)d_in[22];
    const float* f3W   = (const float*)d_in[23]; const float* f3b  = (const float*)d_in[24];
    const float* oW    = (const float*)d_in[25]; const float* ob   = (const float*)d_in[26];

    void *px1, *px, *ph, *phw, *pxc, *pxc2;
    cudaGetSymbolAddress(&px1,  g_x1);
    cudaGetSymbolAddress(&px,   g_x);
    cudaGetSymbolAddress(&ph,   g_h);
    cudaGetSymbolAddress(&phw,  g_hw);
    cudaGetSymbolAddress(&pxc,  g_xc);
    cudaGetSymbolAddress(&pxc2, g_xc2);
    float* x1  = (float*)px1;
    float* x   = (float*)px;
    float* h   = (float*)ph;
    float* hw  = (float*)phw;
    float* xc  = (float*)pxc;
    float* xc2 = (float*)pxc2;

    // graph preprocessing
    k_zero_deg<<<(NN + 255) / 256, 256>>>();
    k_count<<<(NE + 255) / 256, 256>>>(edges);
    k_dinv<<<(NN + 255) / 256, 256>>>();
    k_scan<<<1, 1024>>>();
    k_fill<<<(NE + 255) / 256, 256>>>(edges);

    // BasicBlock
    dim3 gbb2((881 + BN - 1) / BN, (NN + BM - 1) / BM);
    k_sgemm<2><<<gbb2, 256>>>(cid, bb2W, bb2b, thr, x1, NN, 881, 881);
    dim3 gbb3((256 + BN - 1) / BN, (NN + BM - 1) / BM);
    k_sgemm<1><<<gbb3, 256>>>(x1, bb3W, bb3b, nullptr, x, NN, 256, 881);

    // GCN layers
    dim3 g256(2, (NN + BM - 1) / BM);
    dim3 g128(1, (NN + BM - 1) / BM);
    k_sgemm<0><<<g256, 256>>>(x, g1W, nullptr, nullptr, hw, NN, 256, 256);
    k_gather<<<NN, 256>>>(hw, g1b, h, 256);
    k_sgemm<0><<<g256, 256>>>(h, g2W, nullptr, nullptr, hw, NN, 256, 256);
    k_gather<<<NN, 256>>>(hw, g2b, x, 256);
    k_sgemm<0><<<g256, 256>>>(x, g3W, nullptr, nullptr, hw, NN, 256, 256);
    k_gather<<<NN, 256>>>(hw, g3b, h, 256);
    k_sgemm<0><<<g128, 256>>>(h, g4W, nullptr, nullptr, hw, NN, 128, 256);
    k_gather<<<NN, 128>>>(hw, g4b, x, 128);
    k_sgemm<0><<<g128, 256>>>(x, g5W, nullptr, nullptr, hw, NN, 128, 128);
    k_gather<<<NN, 128>>>(hw, g5b, h, 128);

    // pair readout
    k_pair<<<NB, 256>>>(h, i1, i2, xc);
    dim3 gf1((1024 + BN - 1) / BN, (NB + BM - 1) / BM);
    k_sgemm<1><<<gf1, 256>>>(xc, f1W, f1b, nullptr, xc2, NB, 1024, 256);
    dim3 gf2(2, (NB + BM - 1) / BM);
    k_sgemm<1><<<gf2, 256>>>(xc2, f2W, f2b, nullptr, xc, NB, 256, 1024);
    dim3 gf3(1, (NB + BM - 1) / BM);
    k_sgemm<1><<<gf3, 256>>>(xc, f3W, f3b, nullptr, xc2, NB, 64, 256);
    k_out<<<(NB * 2 + 255) / 256, 256>>>(xc2, oW, ob, (float*)d_out);
}

// round 2
// speedup vs baseline: 2.2422x; 2.2422x over previous
#include <cuda_runtime.h>
#include <math.h>

#define NN 30000
#define NE 480000
#define NB 4096
#define NSB 118   // scan blocks: ceil(30000/256)

// ---------------- device scratch (no allocations allowed) ----------------
__device__ float g_x1[NN * 881];    // after bb_fc2 (+relu+softthr)
__device__ float g_x [NN * 256];    // ping
__device__ float g_h [NN * 256];    // pong
__device__ float g_hw[NN * 256];    // H @ W scratch
__device__ float g_dinv[NN];
__device__ int   g_deg[NN];
__device__ int   g_cnt[NN];
__device__ int   g_rowptr[NN + 1];
__device__ int   g_col[NE];
__device__ float g_wgt[NE];
__device__ float g_xc [NB * 1024];
__device__ float g_xc2[NB * 1024];
__device__ int   g_bsum[128];
__device__ int   g_boff[128];

// ---------------- graph preprocessing ----------------
__global__ void k_zero_deg() {
    int i = blockIdx.x * blockDim.x + threadIdx.x;
    if (i < NN) { g_deg[i] = 0; g_cnt[i] = 0; }
}

// edges layout: [2, NE] row-major; src = edges[0..NE), dst = edges[NE..2NE)
__global__ void k_count(const int* __restrict__ edges) {
    int e = blockIdx.x * blockDim.x + threadIdx.x;
    if (e < NE) atomicAdd(&g_deg[edges[NE + e]], 1);
}

__global__ void k_dinv() {
    int i = blockIdx.x * blockDim.x + threadIdx.x;
    if (i < NN) g_dinv[i] = rsqrtf((float)(g_deg[i] + 1));  // +1 self loop
}

// blocked scan: A) per-block exclusive scan + block sums
__global__ void k_scanA() {
    __shared__ int sh[256];
    int tid = threadIdx.x;
    int i = blockIdx.x * 256 + tid;
    int v = (i < NN) ? g_deg[i] : 0;
    sh[tid] = v;
    __syncthreads();
#pragma unroll
    for (int off = 1; off < 256; off <<= 1) {
        int t = (tid >= off) ? sh[tid - off] : 0;
        __syncthreads();
        sh[tid] += t;
        __syncthreads();
    }
    if (i < NN) g_rowptr[i] = sh[tid] - v;   // exclusive (local)
    if (tid == 255) g_bsum[blockIdx.x] = sh[255];
}

// B) scan the block sums (exclusive) in one block
__global__ void k_scanB() {
    __shared__ int sh[128];
    int tid = threadIdx.x;
    int v = (tid < NSB) ? g_bsum[tid] : 0;
    sh[tid] = v;
    __syncthreads();
#pragma unroll
    for (int off = 1; off < 128; off <<= 1) {
        int t = (tid >= off) ? sh[tid - off] : 0;
        __syncthreads();
        sh[tid] += t;
        __syncthreads();
    }
    if (tid < NSB) g_boff[tid] = sh[tid] - v;
    if (tid == 127) g_rowptr[NN] = sh[127];  // total
}

// C) add block offsets
__global__ void k_scanC() {
    int i = blockIdx.x * 256 + threadIdx.x;
    if (i < NN) g_rowptr[i] += g_boff[blockIdx.x];
}

__global__ void k_fill(const int* __restrict__ edges) {
    int e = blockIdx.x * blockDim.x + threadIdx.x;
    if (e < NE) {
        int s = edges[e];
        int d = edges[NE + e];
        int pos = g_rowptr[d] + atomicAdd(&g_cnt[d], 1);
        g_col[pos] = s;
        g_wgt[pos] = g_dinv[s] * g_dinv[d];
    }
}

// ---------------- SGEMM: C[M,N] = A[M,K] @ B[K,N] (+bias, epilogue) --------
// EPI: 0 = none, 1 = relu, 2 = relu then soft-threshold (== max(z - thr, 0))
#define BM 128
#define BN 128
#define BK 16
#define AP 132   // padded As row (2-way instead of 16-way store conflict)

template <int EPI>
__global__ __launch_bounds__(256, 2) void k_sgemm(
    const float* __restrict__ A, const float* __restrict__ B,
    const float* __restrict__ bias, const float* __restrict__ thr_p,
    float* __restrict__ C, int M, int N, int K)
{
    __shared__ float As[2][BK][AP];
    __shared__ float Bs[2][BK][BN];
    int tid = threadIdx.x;
    int row0 = blockIdx.y * BM, col0 = blockIdx.x * BN;
    int tx = tid & 15, ty = tid >> 4;

    // per-thread load coordinates (constant across tiles)
    int ar[8], ac[8], br[8], bc[8];
#pragma unroll
    for (int i = 0; i < 8; i++) {
        int idx = i * 256 + tid;
        ar[i] = idx >> 4;  ac[i] = idx & 15;
        br[i] = idx >> 7;  bc[i] = idx & 127;
    }

    float acc[8][8];
#pragma unroll
    for (int i = 0; i < 8; i++)
#pragma unroll
        for (int j = 0; j < 8; j++) acc[i][j] = 0.f;

    float ldA[8], ldB[8];
    int nt = (K + BK - 1) / BK;

    // preload tile 0
#pragma unroll
    for (int i = 0; i < 8; i++) {
        int gr = row0 + ar[i], gc = ac[i];
        ldA[i] = (gr < M && gc < K) ? A[(long)gr * K + gc] : 0.f;
        int hr = br[i], hc = col0 + bc[i];
        ldB[i] = (hr < K && hc < N) ? B[(long)hr * N + hc] : 0.f;
    }
#pragma unroll
    for (int i = 0; i < 8; i++) { As[0][ac[i]][ar[i]] = ldA[i]; Bs[0][br[i]][bc[i]] = ldB[i]; }
    __syncthreads();

    int cur = 0;
    for (int t = 0; t < nt; t++) {
        int kn = (t + 1) * BK;
        if (t + 1 < nt) {
#pragma unroll
            for (int i = 0; i < 8; i++) {
                int gr = row0 + ar[i], gc = kn + ac[i];
                ldA[i] = (gr < M && gc < K) ? A[(long)gr * K + gc] : 0.f;
                int hr = kn + br[i], hc = col0 + bc[i];
                ldB[i] = (hr < K && hc < N) ? B[(long)hr * N + hc] : 0.f;
            }
        }
#pragma unroll
        for (int kk = 0; kk < BK; kk++) {
            float4 a0 = *(const float4*)&As[cur][kk][ty * 8];
            float4 a1 = *(const float4*)&As[cur][kk][ty * 8 + 4];
            float4 b0 = *(const float4*)&Bs[cur][kk][tx * 8];
            float4 b1 = *(const float4*)&Bs[cur][kk][tx * 8 + 4];
            float ra[8] = {a0.x, a0.y, a0.z, a0.w, a1.x, a1.y, a1.z, a1.w};
            float rb[8] = {b0.x, b0.y, b0.z, b0.w, b1.x, b1.y, b1.z, b1.w};
#pragma unroll
            for (int i = 0; i < 8; i++)
#pragma unroll
                for (int j = 0; j < 8; j++) acc[i][j] = fmaf(ra[i], rb[j], acc[i][j]);
        }
        if (t + 1 < nt) {
            int nxt = cur ^ 1;
#pragma unroll
            for (int i = 0; i < 8; i++) { As[nxt][ac[i]][ar[i]] = ldA[i]; Bs[nxt][br[i]][bc[i]] = ldB[i]; }
            __syncthreads();
            cur = nxt;
        }
    }

    float thr = (EPI == 2) ? thr_p[0] : 0.f;
#pragma unroll
    for (int i = 0; i < 8; i++) {
        int gr = row0 + ty * 8 + i;
        if (gr >= M) continue;
#pragma unroll
        for (int j = 0; j < 8; j++) {
            int gc = col0 + tx * 8 + j;
            if (gc >= N) continue;
            float v = acc[i][j] + (bias ? bias[gc] : 0.f);
            if (EPI == 1) v = fmaxf(v, 0.f);
            if (EPI == 2) { v = fmaxf(v, 0.f); v = fmaxf(v - thr, 0.f); }
            C[(long)gr * N + gc] = v;
        }
    }
}

// ---------------- GCN gather: out = elu(segment_sum(msg) + selfloop + bias) --
// block = (F/4, 4): 4 nodes per block, float4 lanes, edge loop unrolled x4
__global__ void k_gather(const float* __restrict__ hw, const float* __restrict__ bias,
                         float* __restrict__ out, int F)
{
    int n = blockIdx.x * 4 + threadIdx.y;
    if (n >= NN) return;
    int f4 = threadIdx.x;
    int Fq = F >> 2;
    const float4* __restrict__ hw4 = (const float4*)hw;
    float d = g_dinv[n];
    float c = d * d;
    float4 sv = hw4[(long)n * Fq + f4];
    float ax = sv.x * c, ay = sv.y * c, az = sv.z * c, aw = sv.w * c;
    int s = g_rowptr[n], e = g_rowptr[n + 1];
    int i = s;
    for (; i + 4 <= e; i += 4) {
        int   c0 = g_col[i],   c1 = g_col[i + 1], c2 = g_col[i + 2], c3 = g_col[i + 3];
        float w0 = g_wgt[i],  w1 = g_wgt[i + 1], w2 = g_wgt[i + 2], w3 = g_wgt[i + 3];
        float4 v0 = hw4[(long)c0 * Fq + f4];
        float4 v1 = hw4[(long)c1 * Fq + f4];
        float4 v2 = hw4[(long)c2 * Fq + f4];
        float4 v3 = hw4[(long)c3 * Fq + f4];
        ax += w0 * v0.x + w1 * v1.x + w2 * v2.x + w3 * v3.x;
        ay += w0 * v0.y + w1 * v1.y + w2 * v2.y + w3 * v3.y;
        az += w0 * v0.z + w1 * v1.z + w2 * v2.z + w3 * v3.z;
        aw += w0 * v0.w + w1 * v1.w + w2 * v2.w + w3 * v3.w;
    }
    for (; i < e; i++) {
        int c0 = g_col[i]; float w0 = g_wgt[i];
        float4 v0 = hw4[(long)c0 * Fq + f4];
        ax += w0 * v0.x; ay += w0 * v0.y; az += w0 * v0.z; aw += w0 * v0.w;
    }
    float4 b = ((const float4*)bias)[f4];
    ax += b.x; ay += b.y; az += b.z; aw += b.w;
    float4 r;
    r.x = ax > 0.f ? ax : expm1f(ax);
    r.y = ay > 0.f ? ay : expm1f(ay);
    r.z = az > 0.f ? az : expm1f(az);
    r.w = aw > 0.f ? aw : expm1f(aw);
    ((float4*)out)[(long)n * Fq + f4] = r;
}

// ---------------- pair readout: concat + L2 normalize ----------------
__global__ void k_pair(const float* __restrict__ h,
                       const int* __restrict__ i1, const int* __restrict__ i2,
                       float* __restrict__ xc)
{
    int p = blockIdx.x;
    int f = threadIdx.x;  // 256
    float v = (f < 128) ? h[(long)i1[p] * 128 + f] : h[(long)i2[p] * 128 + (f - 128)];
    __shared__ float red[256];
    red[f] = v * v;
    __syncthreads();
    for (int off = 128; off > 0; off >>= 1) {
        if (f < off) red[f] += red[f + off];
        __syncthreads();
    }
    float norm = fmaxf(sqrtf(red[0]), 1e-12f);
    xc[(long)p * 256 + f] = v / norm;
}

// ---------------- final 64->2 ----------------
__global__ void k_out(const float* __restrict__ x, const float* __restrict__ W,
                      const float* __restrict__ b, float* __restrict__ out)
{
    int idx = blockIdx.x * blockDim.x + threadIdx.x;
    if (idx >= NB * 2) return;
    int p = idx >> 1, c = idx & 1;
    float acc = b[c];
#pragma unroll
    for (int k = 0; k < 64; k++) acc += x[p * 64 + k] * W[k * 2 + c];
    out[idx] = acc;
}

// ---------------- launch ----------------
extern "C" void kernel_launch(void* const* d_in, const int* in_sizes, int n_in,
                              void* d_out, int out_size)
{
    const float* cid   = (const float*)d_in[0];
    const int*   edges = (const int*)  d_in[1];   // jax x64 disabled -> int32
    const int*   i1    = (const int*)  d_in[2];
    const int*   i2    = (const int*)  d_in[3];
    const float* thr   = (const float*)d_in[4];
    const float* bb2W  = (const float*)d_in[5];  const float* bb2b = (const float*)d_in[6];
    const float* bb3W  = (const float*)d_in[7];  const float* bb3b = (const float*)d_in[8];
    const float* g1W   = (const float*)d_in[9];  const float* g1b  = (const float*)d_in[10];
    const float* g2W   = (const float*)d_in[11]; const float* g2b  = (const float*)d_in[12];
    const float* g3W   = (const float*)d_in[13]; const float* g3b  = (const float*)d_in[14];
    const float* g4W   = (const float*)d_in[15]; const float* g4b  = (const float*)d_in[16];
    const float* g5W   = (const float*)d_in[17]; const float* g5b  = (const float*)d_in[18];
    const float* f1W   = (const float*)d_in[19]; const float* f1b  = (const float*)d_in[20];
    const float* f2W   = (const float*)d_in[21]; const float* f2b  = (const float*)d_in[22];
    const float* f3W   = (const float*)d_in[23]; const float* f3b  = (const float*)d_in[24];
    const float* oW    = (const float*)d_in[25]; const float* ob   = (const float*)d_in[26];

    void *px1, *px, *ph, *phw, *pxc, *pxc2;
    cudaGetSymbolAddress(&px1,  g_x1);
    cudaGetSymbolAddress(&px,   g_x);
    cudaGetSymbolAddress(&ph,   g_h);
    cudaGetSymbolAddress(&phw,  g_hw);
    cudaGetSymbolAddress(&pxc,  g_xc);
    cudaGetSymbolAddress(&pxc2, g_xc2);
    float* x1  = (float*)px1;
    float* x   = (float*)px;
    float* h   = (float*)ph;
    float* hw  = (float*)phw;
    float* xc  = (float*)pxc;
    float* xc2 = (float*)pxc2;

    // graph preprocessing
    k_zero_deg<<<(NN + 255) / 256, 256>>>();
    k_count<<<(NE + 255) / 256, 256>>>(edges);
    k_dinv<<<(NN + 255) / 256, 256>>>();
    k_scanA<<<NSB, 256>>>();
    k_scanB<<<1, 128>>>();
    k_scanC<<<NSB, 256>>>();
    k_fill<<<(NE + 255) / 256, 256>>>(edges);

    // BasicBlock
    dim3 gbb2((881 + BN - 1) / BN, (NN + BM - 1) / BM);
    k_sgemm<2><<<gbb2, 256>>>(cid, bb2W, bb2b, thr, x1, NN, 881, 881);
    dim3 gbb3((256 + BN - 1) / BN, (NN + BM - 1) / BM);
    k_sgemm<1><<<gbb3, 256>>>(x1, bb3W, bb3b, nullptr, x, NN, 256, 881);

    // GCN layers
    dim3 g256(2, (NN + BM - 1) / BM);
    dim3 g128(1, (NN + BM - 1) / BM);
    dim3 gat256(64, 4);
    dim3 gat128(32, 4);
    int  ngb = (NN + 3) / 4;
    k_sgemm<0><<<g256, 256>>>(x, g1W, nullptr, nullptr, hw, NN, 256, 256);
    k_gather<<<ngb, gat256>>>(hw, g1b, h, 256);
    k_sgemm<0><<<g256, 256>>>(h, g2W, nullptr, nullptr, hw, NN, 256, 256);
    k_gather<<<ngb, gat256>>>(hw, g2b, x, 256);
    k_sgemm<0><<<g256, 256>>>(x, g3W, nullptr, nullptr, hw, NN, 256, 256);
    k_gather<<<ngb, gat256>>>(hw, g3b, h, 256);
    k_sgemm<0><<<g128, 256>>>(h, g4W, nullptr, nullptr, hw, NN, 128, 256);
    k_gather<<<ngb, gat128>>>(hw, g4b, x, 128);
    k_sgemm<0><<<g128, 256>>>(x, g5W, nullptr, nullptr, hw, NN, 128, 128);
    k_gather<<<ngb, gat128>>>(hw, g5b, h, 128);

    // pair readout
    k_pair<<<NB, 256>>>(h, i1, i2, xc);
    dim3 gf1((1024 + BN - 1) / BN, (NB + BM - 1) / BM);
    k_sgemm<1><<<gf1, 256>>>(xc, f1W, f1b, nullptr, xc2, NB, 1024, 256);
    dim3 gf2(2, (NB + BM - 1) / BM);
    k_sgemm<1><<<gf2, 256>>>(xc2, f2W, f2b, nullptr, xc, NB, 256, 1024);
    dim3 gf3(1, (NB + BM - 1) / BM);
    k_sgemm<1><<<gf3, 256>>>(xc, f3W, f3b, nullptr, xc2, NB, 64, 256);
    k_out<<<(NB * 2 + 255) / 256, 256>>>(xc2, oW, ob, (float*)d_out);
}

// round 5
// speedup vs baseline: 2.8162x; 1.2560x over previous
#include <cuda_runtime.h>
#include <math.h>
#include <stdint.h>

#define NN 30000
#define NE 480000
#define NB 4096
#define NSB 118   // scan blocks: ceil(30000/256)

// ---------------- device scratch (no allocations allowed) ----------------
__device__ float g_x1[NN * 896];    // after bb_fc2, row stride 896 (zero-padded)
__device__ float g_x [NN * 256];
__device__ float g_h [NN * 256];
__device__ float g_hw[NN * 256];
__device__ float g_dinv[NN];
__device__ int   g_deg[NN];
__device__ int   g_cnt[NN];
__device__ int   g_rowptr[NN + 1];
__device__ int   g_col[NE];
__device__ float g_wgt[NE];
__device__ float g_xc [NB * 1024];
__device__ float g_xc2[NB * 1024];
__device__ int   g_bsum[128];
__device__ int   g_boff[128];

// transposed weights, packed into one buffer
#define OFF_BB2 0
#define OFF_BB3 (OFF_BB2 + 881*881)
#define OFF_G1  (OFF_BB3 + 256*881)
#define OFF_G2  (OFF_G1  + 256*256)
#define OFF_G3  (OFF_G2  + 256*256)
#define OFF_G4  (OFF_G3  + 256*256)
#define OFF_G5  (OFF_G4  + 128*256)
#define OFF_F1  (OFF_G5  + 128*128)
#define OFF_F2  (OFF_F1  + 1024*256)
#define WT_TOT  (OFF_F2  + 256*1024)
__device__ float g_wt[WT_TOT];

// ---------------- helpers ----------------
__device__ __forceinline__ uint32_t tf32b(float v) {
    float o; asm("cvt.rna.tf32.f32 %0, %1;" : "=f"(o) : "f"(v));
    return __float_as_uint(o);
}

// ---------------- graph preprocessing ----------------
__global__ void k_zero_deg() {
    int i = blockIdx.x * blockDim.x + threadIdx.x;
    if (i < NN) { g_deg[i] = 0; g_cnt[i] = 0; }
}
__global__ void k_count(const int* __restrict__ edges) {
    int e = blockIdx.x * blockDim.x + threadIdx.x;
    if (e < NE) atomicAdd(&g_deg[edges[NE + e]], 1);
}
__global__ void k_dinv() {
    int i = blockIdx.x * blockDim.x + threadIdx.x;
    if (i < NN) g_dinv[i] = rsqrtf((float)(g_deg[i] + 1));
}
__global__ void k_scanA() {
    __shared__ int sh[256];
    int tid = threadIdx.x;
    int i = blockIdx.x * 256 + tid;
    int v = (i < NN) ? g_deg[i] : 0;
    sh[tid] = v;
    __syncthreads();
#pragma unroll
    for (int off = 1; off < 256; off <<= 1) {
        int t = (tid >= off) ? sh[tid - off] : 0;
        __syncthreads();
        sh[tid] += t;
        __syncthreads();
    }
    if (i < NN) g_rowptr[i] = sh[tid] - v;
    if (tid == 255) g_bsum[blockIdx.x] = sh[255];
}
__global__ void k_scanB() {
    __shared__ int sh[128];
    int tid = threadIdx.x;
    int v = (tid < NSB) ? g_bsum[tid] : 0;
    sh[tid] = v;
    __syncthreads();
#pragma unroll
    for (int off = 1; off < 128; off <<= 1) {
        int t = (tid >= off) ? sh[tid - off] : 0;
        __syncthreads();
        sh[tid] += t;
        __syncthreads();
    }
    if (tid < NSB) g_boff[tid] = sh[tid] - v;
    if (tid == 127) g_rowptr[NN] = sh[127];
}
__global__ void k_scanC() {
    int i = blockIdx.x * 256 + threadIdx.x;
    if (i < NN) g_rowptr[i] += g_boff[blockIdx.x];
}
__global__ void k_fill(const int* __restrict__ edges) {
    int e = blockIdx.x * blockDim.x + threadIdx.x;
    if (e < NE) {
        int s = edges[e];
        int d = edges[NE + e];
        int pos = g_rowptr[d] + atomicAdd(&g_cnt[d], 1);
        g_col[pos] = s;
        g_wgt[pos] = g_dinv[s] * g_dinv[d];
    }
}

// ---------------- weight transpose: dst[C x R] = src[R x C]^T ----------------
__global__ void k_transpose(const float* __restrict__ src, float* __restrict__ dst, int R, int C) {
    __shared__ float t[32][33];
    int c0 = blockIdx.x * 32, r0 = blockIdx.y * 32;
    int x = threadIdx.x, y = threadIdx.y;  // 32 x 8
#pragma unroll
    for (int i = 0; i < 4; i++) {
        int r = r0 + y + i * 8;
        if (r < R && c0 + x < C) t[y + i * 8][x] = src[(long)r * C + c0 + x];
    }
    __syncthreads();
#pragma unroll
    for (int i = 0; i < 4; i++) {
        int c = c0 + y + i * 8;
        if (c < C && r0 + x < R) dst[(long)c * R + r0 + x] = t[x][y + i * 8];
    }
}

// ---------------- tf32 mma.sync GEMM ----------------
// C[M,N] = A[M,K](stride lda) @ Bt[N,K](stride K)^T ; output stride ldc;
// cols [N, fillw) written as 0. EPI: 0 none, 1 relu+bias, 2 relu+softthr+bias
// Block 128x128, BK=32, 8 warps as 2x4, warp tile 64x32.
#define SMS 36   // smem row stride (floats), conflict-free
template <int EPI>
__global__ __launch_bounds__(256, 2) void k_wgemm(
    const float* __restrict__ A, const float* __restrict__ Bt,
    const float* __restrict__ bias, const float* __restrict__ thr_p,
    float* __restrict__ C, int M, int N, int K, int lda, int ldc, int fillw)
{
    __shared__ uint32_t smA[128 * SMS];
    __shared__ uint32_t smB[128 * SMS];
    int tid = threadIdx.x, wid = tid >> 5, lane = tid & 31;
    int row0 = blockIdx.y * 128, col0 = blockIdx.x * 128;
    int wr = wid >> 2, wc = wid & 3;     // warp grid 2 x 4
    int lr = tid >> 5, lk = tid & 31;    // load coords
    int q = lane >> 2, t4 = lane & 3;    // quad / thread-in-quad

    float acc[16][4];                    // [tm*4+tn][c0..c3]
#pragma unroll
    for (int i = 0; i < 16; i++)
#pragma unroll
        for (int j = 0; j < 4; j++) acc[i][j] = 0.f;

    int nch = (K + 31) / 32;
    for (int ch = 0; ch < nch; ch++) {
        int k0 = ch * 32;
        __syncthreads();
        // load A tile 128x32 and B tile 128x32 (tf32-converted)
#pragma unroll
        for (int i = 0; i < 16; i++) {
            int r = lr + i * 8;
            int gk = k0 + lk;
            int gr = row0 + r;
            smA[r * SMS + lk] = (gr < M && gk < K) ? tf32b(A[(long)gr * lda + gk]) : 0u;
            int gn = col0 + r;
            smB[r * SMS + lk] = (gn < N && gk < K) ? tf32b(Bt[(long)gn * K + gk]) : 0u;
        }
        __syncthreads();
#pragma unroll
        for (int s = 0; s < 4; s++) {
            int kk = s * 8 + t4;
            uint32_t af[4][4], bf[4][2];
#pragma unroll
            for (int tm = 0; tm < 4; tm++) {
                int r = wr * 64 + tm * 16 + q;
                af[tm][0] = smA[r * SMS + kk];
                af[tm][1] = smA[(r + 8) * SMS + kk];
                af[tm][2] = smA[r * SMS + kk + 4];
                af[tm][3] = smA[(r + 8) * SMS + kk + 4];
            }
#pragma unroll
            for (int tn = 0; tn < 4; tn++) {
                int n = wc * 32 + tn * 8 + q;
                bf[tn][0] = smB[n * SMS + kk];
                bf[tn][1] = smB[n * SMS + kk + 4];
            }
#pragma unroll
            for (int tm = 0; tm < 4; tm++)
#pragma unroll
                for (int tn = 0; tn < 4; tn++) {
                    float* c = acc[tm * 4 + tn];
                    asm volatile(
                        "mma.sync.aligned.m16n8k8.row.col.f32.tf32.tf32.f32 "
                        "{%0,%1,%2,%3}, {%4,%5,%6,%7}, {%8,%9}, {%0,%1,%2,%3};"
                        : "+f"(c[0]), "+f"(c[1]), "+f"(c[2]), "+f"(c[3])
                        : "r"(af[tm][0]), "r"(af[tm][1]), "r"(af[tm][2]), "r"(af[tm][3]),
                          "r"(bf[tn][0]), "r"(bf[tn][1]));
                }
        }
    }

    // epilogue
    float thr = (EPI == 2) ? thr_p[0] : 0.f;
#pragma unroll
    for (int tm = 0; tm < 4; tm++) {
#pragma unroll
        for (int half = 0; half < 2; half++) {
            int gr = row0 + wr * 64 + tm * 16 + q + half * 8;
            if (gr >= M) continue;
#pragma unroll
            for (int tn = 0; tn < 4; tn++) {
#pragma unroll
                for (int cc = 0; cc < 2; cc++) {
                    int gc = col0 + wc * 32 + tn * 8 + 2 * t4 + cc;
                    if (gc >= fillw) continue;
                    float v = 0.f;
                    if (gc < N) {
                        v = acc[tm * 4 + tn][half * 2 + cc];
                        if (EPI != 0) v += bias[gc];
                        if (EPI == 1) v = fmaxf(v, 0.f);
                        if (EPI == 2) v = fmaxf(v - thr, 0.f);
                    }
                    C[(long)gr * ldc + gc] = v;
                }
            }
        }
    }
}

// ---------------- fp32 SGEMM (small tail layer) ----------------
#define BM 128
#define BN 128
#define BK 16
#define AP 132
template <int EPI>
__global__ __launch_bounds__(256, 2) void k_sgemm(
    const float* __restrict__ A, const float* __restrict__ B,
    const float* __restrict__ bias, const float* __restrict__ thr_p,
    float* __restrict__ C, int M, int N, int K)
{
    __shared__ float As[2][BK][AP];
    __shared__ float Bs[2][BK][BN];
    int tid = threadIdx.x;
    int row0 = blockIdx.y * BM, col0 = blockIdx.x * BN;
    int tx = tid & 15, ty = tid >> 4;
    int ar[8], ac[8], br[8], bc[8];
#pragma unroll
    for (int i = 0; i < 8; i++) {
        int idx = i * 256 + tid;
        ar[i] = idx >> 4;  ac[i] = idx & 15;
        br[i] = idx >> 7;  bc[i] = idx & 127;
    }
    float acc[8][8];
#pragma unroll
    for (int i = 0; i < 8; i++)
#pragma unroll
        for (int j = 0; j < 8; j++) acc[i][j] = 0.f;
    float ldA[8], ldB[8];
    int nt = (K + BK - 1) / BK;
#pragma unroll
    for (int i = 0; i < 8; i++) {
        int gr = row0 + ar[i], gc = ac[i];
        ldA[i] = (gr < M && gc < K) ? A[(long)gr * K + gc] : 0.f;
        int hr = br[i], hc = col0 + bc[i];
        ldB[i] = (hr < K && hc < N) ? B[(long)hr * N + hc] : 0.f;
    }
#pragma unroll
    for (int i = 0; i < 8; i++) { As[0][ac[i]][ar[i]] = ldA[i]; Bs[0][br[i]][bc[i]] = ldB[i]; }
    __syncthreads();
    int cur = 0;
    for (int t = 0; t < nt; t++) {
        int kn = (t + 1) * BK;
        if (t + 1 < nt) {
#pragma unroll
            for (int i = 0; i < 8; i++) {
                int gr = row0 + ar[i], gc = kn + ac[i];
                ldA[i] = (gr < M && gc < K) ? A[(long)gr * K + gc] : 0.f;
                int hr = kn + br[i], hc = col0 + bc[i];
                ldB[i] = (hr < K && hc < N) ? B[(long)hr * N + hc] : 0.f;
            }
        }
#pragma unroll
        for (int kk = 0; kk < BK; kk++) {
            float4 a0 = *(const float4*)&As[cur][kk][ty * 8];
            float4 a1 = *(const float4*)&As[cur][kk][ty * 8 + 4];
            float4 b0 = *(const float4*)&Bs[cur][kk][tx * 8];
            float4 b1 = *(const float4*)&Bs[cur][kk][tx * 8 + 4];
            float ra[8] = {a0.x, a0.y, a0.z, a0.w, a1.x, a1.y, a1.z, a1.w};
            float rb[8] = {b0.x, b0.y, b0.z, b0.w, b1.x, b1.y, b1.z, b1.w};
#pragma unroll
            for (int i = 0; i < 8; i++)
#pragma unroll
                for (int j = 0; j < 8; j++) acc[i][j] = fmaf(ra[i], rb[j], acc[i][j]);
        }
        if (t + 1 < nt) {
            int nxt = cur ^ 1;
#pragma unroll
            for (int i = 0; i < 8; i++) { As[nxt][ac[i]][ar[i]] = ldA[i]; Bs[nxt][br[i]][bc[i]] = ldB[i]; }
            __syncthreads();
            cur = nxt;
        }
    }
    float thr = (EPI == 2) ? thr_p[0] : 0.f;
#pragma unroll
    for (int i = 0; i < 8; i++) {
        int gr = row0 + ty * 8 + i;
        if (gr >= M) continue;
#pragma unroll
        for (int j = 0; j < 8; j++) {
            int gc = col0 + tx * 8 + j;
            if (gc >= N) continue;
            float v = acc[i][j] + (bias ? bias[gc] : 0.f);
            if (EPI == 1) v = fmaxf(v, 0.f);
            if (EPI == 2) { v = fmaxf(v, 0.f); v = fmaxf(v - thr, 0.f); }
            C[(long)gr * N + gc] = v;
        }
    }
}

// ---------------- GCN gather ----------------
__global__ void k_gather(const float* __restrict__ hw, const float* __restrict__ bias,
                         float* __restrict__ out, int F)
{
    int n = blockIdx.x * 4 + threadIdx.y;
    if (n >= NN) return;
    int f4 = threadIdx.x;
    int Fq = F >> 2;
    const float4* __restrict__ hw4 = (const float4*)hw;
    float d = g_dinv[n];
    float c = d * d;
    float4 sv = hw4[(long)n * Fq + f4];
    float ax = sv.x * c, ay = sv.y * c, az = sv.z * c, aw = sv.w * c;
    int s = g_rowptr[n], e = g_rowptr[n + 1];
    int i = s;
    for (; i + 4 <= e; i += 4) {
        int   c0 = g_col[i],  c1 = g_col[i + 1], c2 = g_col[i + 2], c3 = g_col[i + 3];
        float w0 = g_wgt[i],  w1 = g_wgt[i + 1], w2 = g_wgt[i + 2], w3 = g_wgt[i + 3];
        float4 v0 = hw4[(long)c0 * Fq + f4];
        float4 v1 = hw4[(long)c1 * Fq + f4];
        float4 v2 = hw4[(long)c2 * Fq + f4];
        float4 v3 = hw4[(long)c3 * Fq + f4];
        ax += w0 * v0.x + w1 * v1.x + w2 * v2.x + w3 * v3.x;
        ay += w0 * v0.y + w1 * v1.y + w2 * v2.y + w3 * v3.y;
        az += w0 * v0.z + w1 * v1.z + w2 * v2.z + w3 * v3.z;
        aw += w0 * v0.w + w1 * v1.w + w2 * v2.w + w3 * v3.w;
    }
    for (; i < e; i++) {
        int c0 = g_col[i]; float w0 = g_wgt[i];
        float4 v0 = hw4[(long)c0 * Fq + f4];
        ax += w0 * v0.x; ay += w0 * v0.y; az += w0 * v0.z; aw += w0 * v0.w;
    }
    float4 b = ((const float4*)bias)[f4];
    ax += b.x; ay += b.y; az += b.z; aw += b.w;
    float4 r;
    r.x = ax > 0.f ? ax : expm1f(ax);
    r.y = ay > 0.f ? ay : expm1f(ay);
    r.z = az > 0.f ? az : expm1f(az);
    r.w = aw > 0.f ? aw : expm1f(aw);
    ((float4*)out)[(long)n * Fq + f4] = r;
}

// ---------------- pair readout ----------------
__global__ void k_pair(const float* __restrict__ h,
                       const int* __restrict__ i1, const int* __restrict__ i2,
                       float* __restrict__ xc)
{
    int p = blockIdx.x;
    int f = threadIdx.x;
    float v = (f < 128) ? h[(long)i1[p] * 128 + f] : h[(long)i2[p] * 128 + (f - 128)];
    __shared__ float red[256];
    red[f] = v * v;
    __syncthreads();
    for (int off = 128; off > 0; off >>= 1) {
        if (f < off) red[f] += red[f + off];
        __syncthreads();
    }
    float norm = fmaxf(sqrtf(red[0]), 1e-12f);
    xc[(long)p * 256 + f] = v / norm;
}

__global__ void k_out(const float* __restrict__ x, const float* __restrict__ W,
                      const float* __restrict__ b, float* __restrict__ out)
{
    int idx = blockIdx.x * blockDim.x + threadIdx.x;
    if (idx >= NB * 2) return;
    int p = idx >> 1, c = idx & 1;
    float acc = b[c];
#pragma unroll
    for (int k = 0; k < 64; k++) acc += x[p * 64 + k] * W[k * 2 + c];
    out[idx] = acc;
}

// ---------------- launch ----------------
extern "C" void kernel_launch(void* const* d_in, const int* in_sizes, int n_in,
                              void* d_out, int out_size)
{
    const float* cid   = (const float*)d_in[0];
    const int*   edges = (const int*)  d_in[1];
    const int*   i1    = (const int*)  d_in[2];
    const int*   i2    = (const int*)  d_in[3];
    const float* thr   = (const float*)d_in[4];
    const float* bb2W  = (const float*)d_in[5];  const float* bb2b = (const float*)d_in[6];
    const float* bb3W  = (const float*)d_in[7];  const float* bb3b = (const float*)d_in[8];
    const float* g1W   = (const float*)d_in[9];  const float* g1b  = (const float*)d_in[10];
    const float* g2W   = (const float*)d_in[11]; const float* g2b  = (const float*)d_in[12];
    const float* g3W   = (const float*)d_in[13]; const float* g3b  = (const float*)d_in[14];
    const float* g4W   = (const float*)d_in[15]; const float* g4b  = (const float*)d_in[16];
    const float* g5W   = (const float*)d_in[17]; const float* g5b  = (const float*)d_in[18];
    const float* f1W   = (const float*)d_in[19]; const float* f1b  = (const float*)d_in[20];
    const float* f2W   = (const float*)d_in[21]; const float* f2b  = (const float*)d_in[22];
    const float* f3W   = (const float*)d_in[23]; const float* f3b  = (const float*)d_in[24];
    const float* oW    = (const float*)d_in[25]; const float* ob   = (const float*)d_in[26];

    void *px1, *px, *ph, *phw, *pxc, *pxc2, *pwt;
    cudaGetSymbolAddress(&px1,  g_x1);
    cudaGetSymbolAddress(&px,   g_x);
    cudaGetSymbolAddress(&ph,   g_h);
    cudaGetSymbolAddress(&phw,  g_hw);
    cudaGetSymbolAddress(&pxc,  g_xc);
    cudaGetSymbolAddress(&pxc2, g_xc2);
    cudaGetSymbolAddress(&pwt,  g_wt);
    float* x1  = (float*)px1;
    float* x   = (float*)px;
    float* h   = (float*)ph;
    float* hw  = (float*)phw;
    float* xc  = (float*)pxc;
    float* xc2 = (float*)pxc2;
    float* wt  = (float*)pwt;

    // graph preprocessing
    k_zero_deg<<<(NN + 255) / 256, 256>>>();
    k_count<<<(NE + 255) / 256, 256>>>(edges);
    k_dinv<<<(NN + 255) / 256, 256>>>();
    k_scanA<<<NSB, 256>>>();
    k_scanB<<<1, 128>>>();
    k_scanC<<<NSB, 256>>>();
    k_fill<<<(NE + 255) / 256, 256>>>(edges);

    // weight transposes -> [N, K]
    dim3 tb(32, 8);
    k_transpose<<<dim3(28, 28), tb>>>(bb2W, wt + OFF_BB2, 881, 881);
    k_transpose<<<dim3(8, 28),  tb>>>(bb3W, wt + OFF_BB3, 881, 256);
    k_transpose<<<dim3(8, 8),   tb>>>(g1W,  wt + OFF_G1,  256, 256);
    k_transpose<<<dim3(8, 8),   tb>>>(g2W,  wt + OFF_G2,  256, 256);
    k_transpose<<<dim3(8, 8),   tb>>>(g3W,  wt + OFF_G3,  256, 256);
    k_transpose<<<dim3(4, 8),   tb>>>(g4W,  wt + OFF_G4,  256, 128);
    k_transpose<<<dim3(4, 4),   tb>>>(g5W,  wt + OFF_G5,  128, 128);
    k_transpose<<<dim3(32, 8),  tb>>>(f1W,  wt + OFF_F1,  256, 1024);
    k_transpose<<<dim3(8, 32),  tb>>>(f2W,  wt + OFF_F2,  1024, 256);

    int MY = (NN + 127) / 128;  // 235

    // BasicBlock (tf32 mma)
    k_wgemm<2><<<dim3(7, MY), 256>>>(cid, wt + OFF_BB2, bb2b, thr, x1, NN, 881, 881, 881, 896, 896);
    k_wgemm<1><<<dim3(2, MY), 256>>>(x1, wt + OFF_BB3, bb3b, nullptr, x, NN, 256, 881, 896, 256, 256);

    // GCN layers (tf32 mma GEMM + gather)
    dim3 gat256(64, 4), gat128(32, 4);
    int  ngb = (NN + 3) / 4;
    k_wgemm<0><<<dim3(2, MY), 256>>>(x, wt + OFF_G1, nullptr, nullptr, hw, NN, 256, 256, 256, 256, 256);
    k_gather<<<ngb, gat256>>>(hw, g1b, h, 256);
    k_wgemm<0><<<dim3(2, MY), 256>>>(h, wt + OFF_G2, nullptr, nullptr, hw, NN, 256, 256, 256, 256, 256);
    k_gather<<<ngb, gat256>>>(hw, g2b, x, 256);
    k_wgemm<0><<<dim3(2, MY), 256>>>(x, wt + OFF_G3, nullptr, nullptr, hw, NN, 256, 256, 256, 256, 256);
    k_gather<<<ngb, gat256>>>(hw, g3b, h, 256);
    k_wgemm<0><<<dim3(1, MY), 256>>>(h, wt + OFF_G4, nullptr, nullptr, hw, NN, 128, 256, 256, 128, 128);
    k_gather<<<ngb, gat128>>>(hw, g4b, x, 128);
    k_wgemm<0><<<dim3(1, MY), 256>>>(x, wt + OFF_G5, nullptr, nullptr, hw, NN, 128, 128, 128, 128, 128);
    k_gather<<<ngb, gat128>>>(hw, g5b, h, 128);

    // pair readout
    k_pair<<<NB, 256>>>(h, i1, i2, xc);
    k_wgemm<1><<<dim3(8, 32), 256>>>(xc,  wt + OFF_F1, f1b, nullptr, xc2, NB, 1024, 256, 256, 1024, 1024);
    k_wgemm<1><<<dim3(2, 32), 256>>>(xc2, wt + OFF_F2, f2b, nullptr, xc,  NB, 256, 1024, 1024, 256, 256);
    k_sgemm<1><<<dim3(1, 32), 256>>>(xc, f3W, f3b, nullptr, xc2, NB, 64, 256);
    k_out<<<(NB * 2 + 255) / 256, 256>>>(xc2, oW, ob, (float*)d_out);
}

// round 6
// speedup vs baseline: 5.3505x; 1.8999x over previous
#include <cuda_runtime.h>
#include <math.h>
#include <stdint.h>

#define NN 30000
#define NNP 30080   // padded to multiple of 128
#define NE 480000
#define NB 4096
#define NSB 118

// ---------------- device scratch ----------------
__device__ float g_cid[NNP * 896];  // padded + tf32-rounded copy of cid
__device__ float g_x1[NNP * 896];
__device__ float g_x [NNP * 256];
__device__ float g_h [NNP * 256];
__device__ float g_hw[NNP * 256];
__device__ float g_dinv[NN];
__device__ int   g_deg[NN];
__device__ int   g_cnt[NN];
__device__ int   g_rowptr[NN + 1];
__device__ int   g_col[NE];
__device__ float g_wgt[NE];
__device__ float g_xc [NB * 1024];
__device__ float g_xc2[NB * 1024];
__device__ int   g_bsum[128];
__device__ int   g_boff[128];

// transposed (tf32-rounded) weights, padded strides, 16B-aligned offsets
#define OFF_BB2 0                       // 896 x 896
#define OFF_BB3 (OFF_BB2 + 896*896)     // 256 x 896
#define OFF_G1  (OFF_BB3 + 256*896)     // 256 x 256
#define OFF_G2  (OFF_G1  + 256*256)
#define OFF_G3  (OFF_G2  + 256*256)
#define OFF_G4  (OFF_G3  + 256*256)    // 128 x 256
#define OFF_G5  (OFF_G4  + 128*256)    // 128 x 128
#define OFF_F1  (OFF_G5  + 128*128)    // 1024 x 256
#define OFF_F2  (OFF_F1  + 1024*256)   // 256 x 1024
#define WT_TOT  (OFF_F2  + 256*1024)
#define WT_ZERO (OFF_G1)               // zero-init BB2t + BB3t regions
__device__ float g_wt[WT_TOT];

// ---------------- helpers ----------------
__device__ __forceinline__ float tf32r(float v) {
    float o; asm("cvt.rna.tf32.f32 %0, %1;" : "=f"(o) : "f"(v));
    return o;
}
__device__ __forceinline__ uint32_t smem_u32(const void* p) {
    uint32_t a;
    asm("{ .reg .u64 t; cvta.to.shared.u64 t, %1; cvt.u32.u64 %0, t; }" : "=r"(a) : "l"(p));
    return a;
}
#define CP16(d, s) asm volatile("cp.async.cg.shared.global [%0], [%1], 16;" :: "r"(d), "l"(s) : "memory")
#define CPCOMMIT() asm volatile("cp.async.commit_group;" ::: "memory")
template<int W> __device__ __forceinline__ void cp_wait() {
    asm volatile("cp.async.wait_group %0;" :: "n"(W) : "memory");
}

// ---------------- graph preprocessing ----------------
__global__ void k_zero_deg() {
    int i = blockIdx.x * blockDim.x + threadIdx.x;
    if (i < NN) { g_deg[i] = 0; g_cnt[i] = 0; }
}
__global__ void k_count(const int* __restrict__ edges) {
    int e = blockIdx.x * blockDim.x + threadIdx.x;
    if (e < NE) atomicAdd(&g_deg[edges[NE + e]], 1);
}
__global__ void k_dinv() {
    int i = blockIdx.x * blockDim.x + threadIdx.x;
    if (i < NN) g_dinv[i] = rsqrtf((float)(g_deg[i] + 1));
}
__global__ void k_scanA() {
    __shared__ int sh[256];
    int tid = threadIdx.x;
    int i = blockIdx.x * 256 + tid;
    int v = (i < NN) ? g_deg[i] : 0;
    sh[tid] = v;
    __syncthreads();
#pragma unroll
    for (int off = 1; off < 256; off <<= 1) {
        int t = (tid >= off) ? sh[tid - off] : 0;
        __syncthreads();
        sh[tid] += t;
        __syncthreads();
    }
    if (i < NN) g_rowptr[i] = sh[tid] - v;
    if (tid == 255) g_bsum[blockIdx.x] = sh[255];
}
__global__ void k_scanB() {
    __shared__ int sh[128];
    int tid = threadIdx.x;
    int v = (tid < NSB) ? g_bsum[tid] : 0;
    sh[tid] = v;
    __syncthreads();
#pragma unroll
    for (int off = 1; off < 128; off <<= 1) {
        int t = (tid >= off) ? sh[tid - off] : 0;
        __syncthreads();
        sh[tid] += t;
        __syncthreads();
    }
    if (tid < NSB) g_boff[tid] = sh[tid] - v;
    if (tid == 127) g_rowptr[NN] = sh[127];
}
__global__ void k_scanC() {
    int i = blockIdx.x * 256 + threadIdx.x;
    if (i < NN) g_rowptr[i] += g_boff[blockIdx.x];
}
__global__ void k_fill(const int* __restrict__ edges) {
    int e = blockIdx.x * blockDim.x + threadIdx.x;
    if (e < NE) {
        int s = edges[e];
        int d = edges[NE + e];
        int pos = g_rowptr[d] + atomicAdd(&g_cnt[d], 1);
        g_col[pos] = s;
        g_wgt[pos] = g_dinv[s] * g_dinv[d];
    }
}

// ---------------- producers: pad + tf32-round ----------------
__global__ void k_pad_cid(const float* __restrict__ cid) {
    int idx = blockIdx.x * 256 + threadIdx.x;
    if (idx >= NNP * 896) return;
    int row = idx / 896, col = idx - row * 896;
    g_cid[idx] = (row < NN && col < 881) ? tf32r(cid[(long)row * 881 + col]) : 0.f;
}
__global__ void k_zero_wt() {
    int i = blockIdx.x * 256 + threadIdx.x;
    if (i < WT_ZERO) g_wt[i] = 0.f;
}
// dst[c*dld + r] = tf32(src[r*C + c])
__global__ void k_transpose2(const float* __restrict__ src, float* __restrict__ dst,
                             int R, int C, int dld) {
    __shared__ float t[32][33];
    int c0 = blockIdx.x * 32, r0 = blockIdx.y * 32;
    int x = threadIdx.x, y = threadIdx.y;  // 32 x 8
#pragma unroll
    for (int i = 0; i < 4; i++) {
        int r = r0 + y + i * 8;
        if (r < R && c0 + x < C) t[y + i * 8][x] = src[(long)r * C + c0 + x];
    }
    __syncthreads();
#pragma unroll
    for (int i = 0; i < 4; i++) {
        int c = c0 + y + i * 8;
        if (c < C && r0 + x < R) dst[(long)c * dld + r0 + x] = tf32r(t[x][y + i * 8]);
    }
}

// ---------------- tf32 mma.sync GEMM, cp.async double-buffered ----------------
// C[M,N] = A[M,Kpad] @ Bt[N,Kpad]^T. All operands pre-rounded to tf32, rows
// 16B-aligned, K padded to mult of 16, M-rows padded (reads unguarded).
// EPI: 0 none, 1 relu+bias, 2 relu+softthr+bias. CVTOUT: round output to tf32.
#define SMS2 20   // smem row stride in floats (16 data + 4 pad)
template <int EPI, int CVTOUT>
__global__ __launch_bounds__(256, 2) void k_wgemm2(
    const float* __restrict__ A, const float* __restrict__ Bt,
    const float* __restrict__ bias, const float* __restrict__ thr_p,
    float* __restrict__ C, int M, int N, int Kpad, int lda, int ldb, int ldc, int fillw)
{
    __shared__ uint32_t smA[2][128 * SMS2];
    __shared__ uint32_t smB[2][128 * SMS2];
    int tid = threadIdx.x, wid = tid >> 5, lane = tid & 31;
    int row0 = blockIdx.y * 128, col0 = blockIdx.x * 128;
    int wr = wid >> 2, wc = wid & 3;     // warp grid 2 x 4, warp tile 64 x 32
    int q = lane >> 2, t4 = lane & 3;

    // cp.async mapping: 2 granules of 16B each for A and B per thread
    int r0 = tid >> 2, c0 = (tid & 3) << 2;   // r0: 0..63, c0: {0,4,8,12}
    int r1 = r0 + 64;
    const float* pA0 = A + (long)(row0 + r0) * lda + c0;
    const float* pA1 = A + (long)(row0 + r1) * lda + c0;
    const float* pB0 = Bt + (long)(col0 + r0) * ldb + c0;
    const float* pB1 = Bt + (long)(col0 + r1) * ldb + c0;
    uint32_t aA = smem_u32(smA), aB = smem_u32(smB);
    uint32_t dA0 = aA + (r0 * SMS2 + c0) * 4;
    uint32_t dA1 = aA + (r1 * SMS2 + c0) * 4;
    uint32_t dB0 = aB + (r0 * SMS2 + c0) * 4;
    uint32_t dB1 = aB + (r1 * SMS2 + c0) * 4;
    const uint32_t SBo = 128 * SMS2 * 4;

    float acc[16][4];
#pragma unroll
    for (int i = 0; i < 16; i++)
#pragma unroll
        for (int j = 0; j < 4; j++) acc[i][j] = 0.f;

    int nch = Kpad >> 4;
    // prefetch stage 0
    CP16(dA0, pA0); CP16(dA1, pA1); CP16(dB0, pB0); CP16(dB1, pB1);
    CPCOMMIT();

    int buf = 0;
    for (int ch = 0; ch < nch; ch++) {
        if (ch + 1 < nch) {
            int k0 = (ch + 1) << 4;
            uint32_t o = (buf ^ 1) ? SBo : 0u;
            CP16(dA0 + o, pA0 + k0); CP16(dA1 + o, pA1 + k0);
            CP16(dB0 + o, pB0 + k0); CP16(dB1 + o, pB1 + k0);
            CPCOMMIT();
            cp_wait<1>();
        } else {
            cp_wait<0>();
        }
        __syncthreads();
        const uint32_t* SA = smA[buf];
        const uint32_t* SBp = smB[buf];
#pragma unroll
        for (int s = 0; s < 2; s++) {
            int kk = s * 8 + t4;
            uint32_t af[4][4], bf[4][2];
#pragma unroll
            for (int tm = 0; tm < 4; tm++) {
                int r = wr * 64 + tm * 16 + q;
                af[tm][0] = SA[r * SMS2 + kk];
                af[tm][1] = SA[(r + 8) * SMS2 + kk];
                af[tm][2] = SA[r * SMS2 + kk + 4];
                af[tm][3] = SA[(r + 8) * SMS2 + kk + 4];
            }
#pragma unroll
            for (int tn = 0; tn < 4; tn++) {
                int n = wc * 32 + tn * 8 + q;
                bf[tn][0] = SBp[n * SMS2 + kk];
                bf[tn][1] = SBp[n * SMS2 + kk + 4];
            }
#pragma unroll
            for (int tm = 0; tm < 4; tm++)
#pragma unroll
                for (int tn = 0; tn < 4; tn++) {
                    float* c = acc[tm * 4 + tn];
                    asm volatile(
                        "mma.sync.aligned.m16n8k8.row.col.f32.tf32.tf32.f32 "
                        "{%0,%1,%2,%3}, {%4,%5,%6,%7}, {%8,%9}, {%0,%1,%2,%3};"
                        : "+f"(c[0]), "+f"(c[1]), "+f"(c[2]), "+f"(c[3])
                        : "r"(af[tm][0]), "r"(af[tm][1]), "r"(af[tm][2]), "r"(af[tm][3]),
                          "r"(bf[tn][0]), "r"(bf[tn][1]));
                }
        }
        __syncthreads();
        buf ^= 1;
    }

    // epilogue
    float thr = (EPI == 2) ? thr_p[0] : 0.f;
#pragma unroll
    for (int tm = 0; tm < 4; tm++) {
#pragma unroll
        for (int half = 0; half < 2; half++) {
            int gr = row0 + wr * 64 + tm * 16 + q + half * 8;
            if (gr >= M) continue;
#pragma unroll
            for (int tn = 0; tn < 4; tn++) {
#pragma unroll
                for (int cc = 0; cc < 2; cc++) {
                    int gc = col0 + wc * 32 + tn * 8 + 2 * t4 + cc;
                    if (gc >= fillw) continue;
                    float v = 0.f;
                    if (gc < N) {
                        v = acc[tm * 4 + tn][half * 2 + cc];
                        if (EPI != 0) v += bias[gc];
                        if (EPI == 1) v = fmaxf(v, 0.f);
                        if (EPI == 2) { v = fmaxf(v, 0.f); v = fmaxf(v - thr, 0.f); }
                        if (CVTOUT) v = tf32r(v);
                    }
                    C[(long)gr * ldc + gc] = v;
                }
            }
        }
    }
}

// ---------------- fp32 SGEMM (f3 tail layer) ----------------
#define BM 128
#define BN 128
#define BK 16
#define AP 132
template <int EPI>
__global__ __launch_bounds__(256, 2) void k_sgemm(
    const float* __restrict__ A, const float* __restrict__ B,
    const float* __restrict__ bias, const float* __restrict__ thr_p,
    float* __restrict__ C, int M, int N, int K)
{
    __shared__ float As[2][BK][AP];
    __shared__ float Bs[2][BK][BN];
    int tid = threadIdx.x;
    int row0 = blockIdx.y * BM, col0 = blockIdx.x * BN;
    int tx = tid & 15, ty = tid >> 4;
    int ar[8], ac[8], br[8], bc[8];
#pragma unroll
    for (int i = 0; i < 8; i++) {
        int idx = i * 256 + tid;
        ar[i] = idx >> 4;  ac[i] = idx & 15;
        br[i] = idx >> 7;  bc[i] = idx & 127;
    }
    float acc[8][8];
#pragma unroll
    for (int i = 0; i < 8; i++)
#pragma unroll
        for (int j = 0; j < 8; j++) acc[i][j] = 0.f;
    float ldA[8], ldB[8];
    int nt = (K + BK - 1) / BK;
#pragma unroll
    for (int i = 0; i < 8; i++) {
        int gr = row0 + ar[i], gc = ac[i];
        ldA[i] = (gr < M && gc < K) ? A[(long)gr * K + gc] : 0.f;
        int hr = br[i], hc = col0 + bc[i];
        ldB[i] = (hr < K && hc < N) ? B[(long)hr * N + hc] : 0.f;
    }
#pragma unroll
    for (int i = 0; i < 8; i++) { As[0][ac[i]][ar[i]] = ldA[i]; Bs[0][br[i]][bc[i]] = ldB[i]; }
    __syncthreads();
    int cur = 0;
    for (int t = 0; t < nt; t++) {
        int kn = (t + 1) * BK;
        if (t + 1 < nt) {
#pragma unroll
            for (int i = 0; i < 8; i++) {
                int gr = row0 + ar[i], gc = kn + ac[i];
                ldA[i] = (gr < M && gc < K) ? A[(long)gr * K + gc] : 0.f;
                int hr = kn + br[i], hc = col0 + bc[i];
                ldB[i] = (hr < K && hc < N) ? B[(long)hr * N + hc] : 0.f;
            }
        }
#pragma unroll
        for (int kk = 0; kk < BK; kk++) {
            float4 a0 = *(const float4*)&As[cur][kk][ty * 8];
            float4 a1 = *(const float4*)&As[cur][kk][ty * 8 + 4];
            float4 b0 = *(const float4*)&Bs[cur][kk][tx * 8];
            float4 b1 = *(const float4*)&Bs[cur][kk][tx * 8 + 4];
            float ra[8] = {a0.x, a0.y, a0.z, a0.w, a1.x, a1.y, a1.z, a1.w};
            float rb[8] = {b0.x, b0.y, b0.z, b0.w, b1.x, b1.y, b1.z, b1.w};
#pragma unroll
            for (int i = 0; i < 8; i++)
#pragma unroll
                for (int j = 0; j < 8; j++) acc[i][j] = fmaf(ra[i], rb[j], acc[i][j]);
        }
        if (t + 1 < nt) {
            int nxt = cur ^ 1;
#pragma unroll
            for (int i = 0; i < 8; i++) { As[nxt][ac[i]][ar[i]] = ldA[i]; Bs[nxt][br[i]][bc[i]] = ldB[i]; }
            __syncthreads();
            cur = nxt;
        }
    }
    float thr = (EPI == 2) ? thr_p[0] : 0.f;
#pragma unroll
    for (int i = 0; i < 8; i++) {
        int gr = row0 + ty * 8 + i;
        if (gr >= M) continue;
#pragma unroll
        for (int j = 0; j < 8; j++) {
            int gc = col0 + tx * 8 + j;
            if (gc >= N) continue;
            float v = acc[i][j] + (bias ? bias[gc] : 0.f);
            if (EPI == 1) v = fmaxf(v, 0.f);
            if (EPI == 2) { v = fmaxf(v, 0.f); v = fmaxf(v - thr, 0.f); }
            C[(long)gr * N + gc] = v;
        }
    }
}

// ---------------- GCN gather (output tf32-rounded: feeds next GEMM) --------
__global__ void k_gather(const float* __restrict__ hw, const float* __restrict__ bias,
                         float* __restrict__ out, int F)
{
    int n = blockIdx.x * 4 + threadIdx.y;
    if (n >= NN) return;
    int f4 = threadIdx.x;
    int Fq = F >> 2;
    const float4* __restrict__ hw4 = (const float4*)hw;
    float d = g_dinv[n];
    float c = d * d;
    float4 sv = hw4[(long)n * Fq + f4];
    float ax = sv.x * c, ay = sv.y * c, az = sv.z * c, aw = sv.w * c;
    int s = g_rowptr[n], e = g_rowptr[n + 1];
    int i = s;
    for (; i + 4 <= e; i += 4) {
        int   c0 = g_col[i],  c1 = g_col[i + 1], c2 = g_col[i + 2], c3 = g_col[i + 3];
        float w0 = g_wgt[i],  w1 = g_wgt[i + 1], w2 = g_wgt[i + 2], w3 = g_wgt[i + 3];
        float4 v0 = hw4[(long)c0 * Fq + f4];
        float4 v1 = hw4[(long)c1 * Fq + f4];
        float4 v2 = hw4[(long)c2 * Fq + f4];
        float4 v3 = hw4[(long)c3 * Fq + f4];
        ax += w0 * v0.x + w1 * v1.x + w2 * v2.x + w3 * v3.x;
        ay += w0 * v0.y + w1 * v1.y + w2 * v2.y + w3 * v3.y;
        az += w0 * v0.z + w1 * v1.z + w2 * v2.z + w3 * v3.z;
        aw += w0 * v0.w + w1 * v1.w + w2 * v2.w + w3 * v3.w;
    }
    for (; i < e; i++) {
        int c0 = g_col[i]; float w0 = g_wgt[i];
        float4 v0 = hw4[(long)c0 * Fq + f4];
        ax += w0 * v0.x; ay += w0 * v0.y; az += w0 * v0.z; aw += w0 * v0.w;
    }
    float4 b = ((const float4*)bias)[f4];
    ax += b.x; ay += b.y; az += b.z; aw += b.w;
    float4 r;
    r.x = tf32r(ax > 0.f ? ax : expm1f(ax));
    r.y = tf32r(ay > 0.f ? ay : expm1f(ay));
    r.z = tf32r(az > 0.f ? az : expm1f(az));
    r.w = tf32r(aw > 0.f ? aw : expm1f(aw));
    ((float4*)out)[(long)n * Fq + f4] = r;
}

// ---------------- pair readout (output tf32-rounded: feeds f1 GEMM) --------
__global__ void k_pair(const float* __restrict__ h,
                       const int* __restrict__ i1, const int* __restrict__ i2,
                       float* __restrict__ xc)
{
    int p = blockIdx.x;
    int f = threadIdx.x;
    float v = (f < 128) ? h[(long)i1[p] * 128 + f] : h[(long)i2[p] * 128 + (f - 128)];
    __shared__ float red[256];
    red[f] = v * v;
    __syncthreads();
    for (int off = 128; off > 0; off >>= 1) {
        if (f < off) red[f] += red[f + off];
        __syncthreads();
    }
    float norm = fmaxf(sqrtf(red[0]), 1e-12f);
    xc[(long)p * 256 + f] = tf32r(v / norm);
}

__global__ void k_out(const float* __restrict__ x, const float* __restrict__ W,
                      const float* __restrict__ b, float* __restrict__ out)
{
    int idx = blockIdx.x * blockDim.x + threadIdx.x;
    if (idx >= NB * 2) return;
    int p = idx >> 1, c = idx & 1;
    float acc = b[c];
#pragma unroll
    for (int k = 0; k < 64; k++) acc += x[p * 64 + k] * W[k * 2 + c];
    out[idx] = acc;
}

// ---------------- launch ----------------
extern "C" void kernel_launch(void* const* d_in, const int* in_sizes, int n_in,
                              void* d_out, int out_size)
{
    const float* cid   = (const float*)d_in[0];
    const int*   edges = (const int*)  d_in[1];
    const int*   i1    = (const int*)  d_in[2];
    const int*   i2    = (const int*)  d_in[3];
    const float* thr   = (const float*)d_in[4];
    const float* bb2W  = (const float*)d_in[5];  const float* bb2b = (const float*)d_in[6];
    const float* bb3W  = (const float*)d_in[7];  const float* bb3b = (const float*)d_in[8];
    const float* g1W   = (const float*)d_in[9];  const float* g1b  = (const float*)d_in[10];
    const float* g2W   = (const float*)d_in[11]; const float* g2b  = (const float*)d_in[12];
    const float* g3W   = (const float*)d_in[13]; const float* g3b  = (const float*)d_in[14];
    const float* g4W   = (const float*)d_in[15]; const float* g4b  = (const float*)d_in[16];
    const float* g5W   = (const float*)d_in[17]; const float* g5b  = (const float*)d_in[18];
    const float* f1W   = (const float*)d_in[19]; const float* f1b  = (const float*)d_in[20];
    const float* f2W   = (const float*)d_in[21]; const float* f2b  = (const float*)d_in[22];
    const float* f3W   = (const float*)d_in[23]; const float* f3b  = (const float*)d_in[24];
    const float* oW    = (const float*)d_in[25]; const float* ob   = (const float*)d_in[26];

    void *pcid, *px1, *px, *ph, *phw, *pxc, *pxc2, *pwt;
    cudaGetSymbolAddress(&pcid, g_cid);
    cudaGetSymbolAddress(&px1,  g_x1);
    cudaGetSymbolAddress(&px,   g_x);
    cudaGetSymbolAddress(&ph,   g_h);
    cudaGetSymbolAddress(&phw,  g_hw);
    cudaGetSymbolAddress(&pxc,  g_xc);
    cudaGetSymbolAddress(&pxc2, g_xc2);
    cudaGetSymbolAddress(&pwt,  g_wt);
    float* cidp = (float*)pcid;
    float* x1  = (float*)px1;
    float* x   = (float*)px;
    float* h   = (float*)ph;
    float* hw  = (float*)phw;
    float* xc  = (float*)pxc;
    float* xc2 = (float*)pxc2;
    float* wt  = (float*)pwt;

    // graph preprocessing
    k_zero_deg<<<(NN + 255) / 256, 256>>>();
    k_count<<<(NE + 255) / 256, 256>>>(edges);
    k_dinv<<<(NN + 255) / 256, 256>>>();
    k_scanA<<<NSB, 256>>>();
    k_scanB<<<1, 128>>>();
    k_scanC<<<NSB, 256>>>();
    k_fill<<<(NE + 255) / 256, 256>>>(edges);

    // producers: padded tf32 input + transposed tf32 weights
    k_pad_cid<<<(NNP * 896 + 255) / 256, 256>>>(cid);
    k_zero_wt<<<(WT_ZERO + 255) / 256, 256>>>();
    dim3 tb(32, 8);
    k_transpose2<<<dim3(28, 28), tb>>>(bb2W, wt + OFF_BB2, 881, 881, 896);
    k_transpose2<<<dim3(8, 28),  tb>>>(bb3W, wt + OFF_BB3, 881, 256, 896);
    k_transpose2<<<dim3(8, 8),   tb>>>(g1W,  wt + OFF_G1,  256, 256, 256);
    k_transpose2<<<dim3(8, 8),   tb>>>(g2W,  wt + OFF_G2,  256, 256, 256);
    k_transpose2<<<dim3(8, 8),   tb>>>(g3W,  wt + OFF_G3,  256, 256, 256);
    k_transpose2<<<dim3(4, 8),   tb>>>(g4W,  wt + OFF_G4,  256, 128, 256);
    k_transpose2<<<dim3(4, 4),   tb>>>(g5W,  wt + OFF_G5,  128, 128, 128);
    k_transpose2<<<dim3(32, 8),  tb>>>(f1W,  wt + OFF_F1,  256, 1024, 256);
    k_transpose2<<<dim3(8, 32),  tb>>>(f2W,  wt + OFF_F2,  1024, 256, 1024);

    int MY = NNP / 128;  // 235

    // BasicBlock
    k_wgemm2<2,1><<<dim3(7, MY), 256>>>(cidp, wt + OFF_BB2, bb2b, thr, x1,
                                        NN, 881, 896, 896, 896, 896, 896);
    k_wgemm2<1,1><<<dim3(2, MY), 256>>>(x1, wt + OFF_BB3, bb3b, nullptr, x,
                                        NN, 256, 896, 896, 896, 256, 256);

    // GCN layers
    dim3 gat256(64, 4), gat128(32, 4);
    int  ngb = (NN + 3) / 4;
    k_wgemm2<0,0><<<dim3(2, MY), 256>>>(x, wt + OFF_G1, nullptr, nullptr, hw,
                                        NN, 256, 256, 256, 256, 256, 256);
    k_gather<<<ngb, gat256>>>(hw, g1b, h, 256);
    k_wgemm2<0,0><<<dim3(2, MY), 256>>>(h, wt + OFF_G2, nullptr, nullptr, hw,
                                        NN, 256, 256, 256, 256, 256, 256);
    k_gather<<<ngb, gat256>>>(hw, g2b, x, 256);
    k_wgemm2<0,0><<<dim3(2, MY), 256>>>(x, wt + OFF_G3, nullptr, nullptr, hw,
                                        NN, 256, 256, 256, 256, 256, 256);
    k_gather<<<ngb, gat256>>>(hw, g3b, h, 256);
    k_wgemm2<0,0><<<dim3(1, MY), 256>>>(h, wt + OFF_G4, nullptr, nullptr, hw,
                                        NN, 128, 256, 256, 256, 128, 128);
    k_gather<<<ngb, gat128>>>(hw, g4b, x, 128);
    k_wgemm2<0,0><<<dim3(1, MY), 256>>>(x, wt + OFF_G5, nullptr, nullptr, hw,
                                        NN, 128, 128, 128, 128, 128, 128);
    k_gather<<<ngb, gat128>>>(hw, g5b, h, 128);

    // pair readout
    k_pair<<<NB, 256>>>(h, i1, i2, xc);
    k_wgemm2<1,1><<<dim3(8, 32), 256>>>(xc,  wt + OFF_F1, f1b, nullptr, xc2,
                                        NB, 1024, 256, 256, 256, 1024, 1024);
    k_wgemm2<1,0><<<dim3(2, 32), 256>>>(xc2, wt + OFF_F2, f2b, nullptr, xc,
                                        NB, 256, 1024, 1024, 1024, 256, 256);
    k_sgemm<1><<<dim3(1, 32), 256>>>(xc, f3W, f3b, nullptr, xc2, NB, 64, 256);
    k_out<<<(NB * 2 + 255) / 256, 256>>>(xc2, oW, ob, (float*)d_out);
}

// round 8
// speedup vs baseline: 7.3641x; 1.3763x over previous
#include <cuda_runtime.h>
#include <cuda_fp16.h>
#include <math.h>
#include <stdint.h>

#define NN 30000
#define NNP 30080   // padded to multiple of 128
#define NE 480000
#define NB 4096
#define NSB 118

// ---------------- device scratch ----------------
__device__ __align__(16) __half g_cid[NNP * 896];
__device__ __align__(16) __half g_x1[NNP * 896];
__device__ __align__(16) __half g_x [NNP * 256];
__device__ __align__(16) __half g_h [NNP * 256];
__device__ float g_hw[NNP * 256];          // GEMM out / gather in (fp32)
__device__ __align__(16) __half g_pc[NB * 256];    // pair out
__device__ __align__(16) __half g_f1[NB * 1024];   // f1 out
__device__ float g_f2[NB * 256];           // f2 out (feeds fp32 sgemm)
__device__ float g_f3[NB * 64];            // f3 out
__device__ float g_dinv[NN];
__device__ int   g_deg[NN];
__device__ int   g_cnt[NN];
__device__ int   g_rowptr[NN + 1];
__device__ int   g_col[NE];
__device__ float g_wgt[NE];
__device__ int   g_bsum[128];
__device__ int   g_boff[128];

// transposed fp16 weights (element offsets)
#define OFF_BB2 0                       // 896 x 896
#define OFF_BB3 (OFF_BB2 + 896*896)     // 256 x 896
#define OFF_G1  (OFF_BB3 + 256*896)     // 256 x 256
#define OFF_G2  (OFF_G1  + 256*256)
#define OFF_G3  (OFF_G2  + 256*256)
#define OFF_G4  (OFF_G3  + 256*256)    // 128 x 256
#define OFF_G5  (OFF_G4  + 128*256)    // 128 x 128
#define OFF_F1  (OFF_G5  + 128*128)    // 1024 x 256
#define OFF_F2  (OFF_F1  + 1024*256)   // 256 x 1024
#define WT_TOT  (OFF_F2  + 256*1024)
#define WT_ZERO (OFF_G1)               // zero-init BB2t + BB3t pad regions
__device__ __align__(16) __half g_wt[WT_TOT];

// ---------------- helpers ----------------
__device__ __forceinline__ uint32_t smem_u32(const void* p) {
    uint32_t a;
    asm("{ .reg .u64 t; cvta.to.shared.u64 t, %1; cvt.u32.u64 %0, t; }" : "=r"(a) : "l"(p));
    return a;
}
#define CP16(d, s) asm volatile("cp.async.cg.shared.global [%0], [%1], 16;" :: "r"(d), "l"(s) : "memory")
#define CPCOMMIT() asm volatile("cp.async.commit_group;" ::: "memory")
template<int W> __device__ __forceinline__ void cp_wait() {
    asm volatile("cp.async.wait_group %0;" :: "n"(W) : "memory");
}

// ---------------- graph preprocessing ----------------
__global__ void k_zero_deg() {
    int i = blockIdx.x * blockDim.x + threadIdx.x;
    if (i < NN) { g_deg[i] = 0; g_cnt[i] = 0; }
}
__global__ void k_count(const int* __restrict__ edges) {
    int e = blockIdx.x * blockDim.x + threadIdx.x;
    if (e < NE) atomicAdd(&g_deg[edges[NE + e]], 1);
}
__global__ void k_dinv() {
    int i = blockIdx.x * blockDim.x + threadIdx.x;
    if (i < NN) g_dinv[i] = rsqrtf((float)(g_deg[i] + 1));
}
__global__ void k_scanA() {
    __shared__ int sh[256];
    int tid = threadIdx.x;
    int i = blockIdx.x * 256 + tid;
    int v = (i < NN) ? g_deg[i] : 0;
    sh[tid] = v;
    __syncthreads();
#pragma unroll
    for (int off = 1; off < 256; off <<= 1) {
        int t = (tid >= off) ? sh[tid - off] : 0;
        __syncthreads();
        sh[tid] += t;
        __syncthreads();
    }
    if (i < NN) g_rowptr[i] = sh[tid] - v;
    if (tid == 255) g_bsum[blockIdx.x] = sh[255];
}
__global__ void k_scanB() {
    __shared__ int sh[128];
    int tid = threadIdx.x;
    int v = (tid < NSB) ? g_bsum[tid] : 0;
    sh[tid] = v;
    __syncthreads();
#pragma unroll
    for (int off = 1; off < 128; off <<= 1) {
        int t = (tid >= off) ? sh[tid - off] : 0;
        __syncthreads();
        sh[tid] += t;
        __syncthreads();
    }
    if (tid < NSB) g_boff[tid] = sh[tid] - v;
    if (tid == 127) g_rowptr[NN] = sh[127];
}
__global__ void k_scanC() {
    int i = blockIdx.x * 256 + threadIdx.x;
    if (i < NN) g_rowptr[i] += g_boff[blockIdx.x];
}
__global__ void k_fill(const int* __restrict__ edges) {
    int e = blockIdx.x * blockDim.x + threadIdx.x;
    if (e < NE) {
        int s = edges[e];
        int d = edges[NE + e];
        int pos = g_rowptr[d] + atomicAdd(&g_cnt[d], 1);
        g_col[pos] = s;
        g_wgt[pos] = g_dinv[s] * g_dinv[d];
    }
}

// ---------------- producers: pad + fp16-convert ----------------
__global__ void k_pad_cid(const float* __restrict__ cid) {
    int idx = blockIdx.x * 256 + threadIdx.x;
    if (idx >= NNP * 896) return;
    int row = idx / 896, col = idx - row * 896;
    g_cid[idx] = __float2half_rn((row < NN && col < 881) ? cid[(long)row * 881 + col] : 0.f);
}
__global__ void k_zero_wt() {
    int i = blockIdx.x * 256 + threadIdx.x;
    if (i < WT_ZERO) g_wt[i] = __float2half_rn(0.f);
}
// dst[c*dld + r] = fp16(src[r*C + c])
__global__ void k_transpose2(const float* __restrict__ src, __half* __restrict__ dst,
                             int R, int C, int dld) {
    __shared__ float t[32][33];
    int c0 = blockIdx.x * 32, r0 = blockIdx.y * 32;
    int x = threadIdx.x, y = threadIdx.y;  // 32 x 8
#pragma unroll
    for (int i = 0; i < 4; i++) {
        int r = r0 + y + i * 8;
        if (r < R && c0 + x < C) t[y + i * 8][x] = src[(long)r * C + c0 + x];
    }
    __syncthreads();
#pragma unroll
    for (int i = 0; i < 4; i++) {
        int c = c0 + y + i * 8;
        if (c < C && r0 + x < R) dst[(long)c * dld + r0 + x] = __float2half_rn(t[x][y + i * 8]);
    }
}

// ---------------- fp16 mma.sync GEMM, cp.async double-buffered ----------------
// C[M,N] = A[M,Kpad] @ Bt[N,Kpad]^T, fp16 operands, fp32 accum.
// EPI: 0 none, 1 relu+bias, 2 relu+softthr+bias. OUTH: 1 -> half output, 0 -> float.
#define SMSH 40   // smem row stride in halfs (32 data + 8 pad)
template <int EPI, int OUTH>
__global__ __launch_bounds__(256, 2) void k_hgemm(
    const __half* __restrict__ A, const __half* __restrict__ Bt,
    const float* __restrict__ bias, const float* __restrict__ thr_p,
    void* __restrict__ Cv, int M, int N, int Kpad, int lda, int ldb, int ldc, int fillw)
{
    __shared__ __align__(16) __half smA[2][128 * SMSH];
    __shared__ __align__(16) __half smB[2][128 * SMSH];
    int tid = threadIdx.x, wid = tid >> 5, lane = tid & 31;
    int row0 = blockIdx.y * 128, col0 = blockIdx.x * 128;
    int wr = wid >> 2, wc = wid & 3;     // warp grid 2 x 4, warp tile 64 x 32
    int q = lane >> 2, t4 = lane & 3;

    // cp.async mapping: 128 rows x 64B per operand = 512 granules; 2 per thread
    int r0 = tid >> 2, off = (tid & 3) * 8;   // off in halfs
    int r1 = r0 + 64;
    const __half* pA0 = A + (long)(row0 + r0) * lda + off;
    const __half* pA1 = A + (long)(row0 + r1) * lda + off;
    const __half* pB0 = Bt + (long)(col0 + r0) * ldb + off;
    const __half* pB1 = Bt + (long)(col0 + r1) * ldb + off;
    uint32_t aA = smem_u32(smA), aB = smem_u32(smB);
    uint32_t dA0 = aA + (r0 * SMSH + off) * 2;
    uint32_t dA1 = aA + (r1 * SMSH + off) * 2;
    uint32_t dB0 = aB + (r0 * SMSH + off) * 2;
    uint32_t dB1 = aB + (r1 * SMSH + off) * 2;
    const uint32_t SBo = 128 * SMSH * 2;

    float acc[16][4];
#pragma unroll
    for (int i = 0; i < 16; i++)
#pragma unroll
        for (int j = 0; j < 4; j++) acc[i][j] = 0.f;

    int nch = Kpad >> 5;    // 32-K chunks
    CP16(dA0, pA0); CP16(dA1, pA1); CP16(dB0, pB0); CP16(dB1, pB1);
    CPCOMMIT();

    int buf = 0;
    for (int ch = 0; ch < nch; ch++) {
        if (ch + 1 < nch) {
            int k0 = (ch + 1) << 5;
            uint32_t o = (buf ^ 1) ? SBo : 0u;
            CP16(dA0 + o, pA0 + k0); CP16(dA1 + o, pA1 + k0);
            CP16(dB0 + o, pB0 + k0); CP16(dB1 + o, pB1 + k0);
            CPCOMMIT();
            cp_wait<1>();
        } else {
            cp_wait<0>();
        }
        __syncthreads();
        const __half* SA = smA[buf];
        const __half* SB = smB[buf];
#pragma unroll
        for (int s = 0; s < 2; s++) {
            int koff = s * 16 + 2 * t4;
            uint32_t af[4][4], bf[4][2];
#pragma unroll
            for (int tm = 0; tm < 4; tm++) {
                int r = wr * 64 + tm * 16 + q;
                af[tm][0] = *(const uint32_t*)&SA[r * SMSH + koff];
                af[tm][1] = *(const uint32_t*)&SA[(r + 8) * SMSH + koff];
                af[tm][2] = *(const uint32_t*)&SA[r * SMSH + koff + 8];
                af[tm][3] = *(const uint32_t*)&SA[(r + 8) * SMSH + koff + 8];
            }
#pragma unroll
            for (int tn = 0; tn < 4; tn++) {
                int n = wc * 32 + tn * 8 + q;
                bf[tn][0] = *(const uint32_t*)&SB[n * SMSH + koff];
                bf[tn][1] = *(const uint32_t*)&SB[n * SMSH + koff + 8];
            }
#pragma unroll
            for (int tm = 0; tm < 4; tm++)
#pragma unroll
                for (int tn = 0; tn < 4; tn++) {
                    float* c = acc[tm * 4 + tn];
                    asm volatile(
                        "mma.sync.aligned.m16n8k16.row.col.f32.f16.f16.f32 "
                        "{%0,%1,%2,%3}, {%4,%5,%6,%7}, {%8,%9}, {%0,%1,%2,%3};"
                        : "+f"(c[0]), "+f"(c[1]), "+f"(c[2]), "+f"(c[3])
                        : "r"(af[tm][0]), "r"(af[tm][1]), "r"(af[tm][2]), "r"(af[tm][3]),
                          "r"(bf[tn][0]), "r"(bf[tn][1]));
                }
        }
        __syncthreads();
        buf ^= 1;
    }

    // epilogue
    float thr = (EPI == 2) ? thr_p[0] : 0.f;
#pragma unroll
    for (int tm = 0; tm < 4; tm++) {
#pragma unroll
        for (int half_ = 0; half_ < 2; half_++) {
            int gr = row0 + wr * 64 + tm * 16 + q + half_ * 8;
            if (gr >= M) continue;
#pragma unroll
            for (int tn = 0; tn < 4; tn++) {
#pragma unroll
                for (int cc = 0; cc < 2; cc++) {
                    int gc = col0 + wc * 32 + tn * 8 + 2 * t4 + cc;
                    if (gc >= fillw) continue;
                    float v = 0.f;
                    if (gc < N) {
                        v = acc[tm * 4 + tn][half_ * 2 + cc];
                        if (EPI != 0) v += bias[gc];
                        if (EPI == 1) v = fmaxf(v, 0.f);
                        if (EPI == 2) { v = fmaxf(v, 0.f); v = fmaxf(v - thr, 0.f); }
                    }
                    if (OUTH) ((__half*)Cv)[(long)gr * ldc + gc] = __float2half_rn(v);
                    else      ((float*)Cv)[(long)gr * ldc + gc] = v;
                }
            }
        }
    }
}

// ---------------- fp32 SGEMM (f3 tail layer) ----------------
#define BM 128
#define BN 128
#define BK 16
#define AP 132
template <int EPI>
__global__ __launch_bounds__(256, 2) void k_sgemm(
    const float* __restrict__ A, const float* __restrict__ B,
    const float* __restrict__ bias, const float* __restrict__ thr_p,
    float* __restrict__ C, int M, int N, int K)
{
    __shared__ float As[2][BK][AP];
    __shared__ float Bs[2][BK][BN];
    int tid = threadIdx.x;
    int row0 = blockIdx.y * BM, col0 = blockIdx.x * BN;
    int tx = tid & 15, ty = tid >> 4;
    int ar[8], ac[8], br[8], bc[8];
#pragma unroll
    for (int i = 0; i < 8; i++) {
        int idx = i * 256 + tid;
        ar[i] = idx >> 4;  ac[i] = idx & 15;
        br[i] = idx >> 7;  bc[i] = idx & 127;
    }
    float acc[8][8];
#pragma unroll
    for (int i = 0; i < 8; i++)
#pragma unroll
        for (int j = 0; j < 8; j++) acc[i][j] = 0.f;
    float ldA[8], ldB[8];
    int nt = (K + BK - 1) / BK;
#pragma unroll
    for (int i = 0; i < 8; i++) {
        int gr = row0 + ar[i], gc = ac[i];
        ldA[i] = (gr < M && gc < K) ? A[(long)gr * K + gc] : 0.f;
        int hr = br[i], hc = col0 + bc[i];
        ldB[i] = (hr < K && hc < N) ? B[(long)hr * N + hc] : 0.f;
    }
#pragma unroll
    for (int i = 0; i < 8; i++) { As[0][ac[i]][ar[i]] = ldA[i]; Bs[0][br[i]][bc[i]] = ldB[i]; }
    __syncthreads();
    int cur = 0;
    for (int t = 0; t < nt; t++) {
        int kn = (t + 1) * BK;
        if (t + 1 < nt) {
#pragma unroll
            for (int i = 0; i < 8; i++) {
                int gr = row0 + ar[i], gc = kn + ac[i];
                ldA[i] = (gr < M && gc < K) ? A[(long)gr * K + gc] : 0.f;
                int hr = kn + br[i], hc = col0 + bc[i];
                ldB[i] = (hr < K && hc < N) ? B[(long)hr * N + hc] : 0.f;
            }
        }
#pragma unroll
        for (int kk = 0; kk < BK; kk++) {
            float4 a0 = *(const float4*)&As[cur][kk][ty * 8];
            float4 a1 = *(const float4*)&As[cur][kk][ty * 8 + 4];
            float4 b0 = *(const float4*)&Bs[cur][kk][tx * 8];
            float4 b1 = *(const float4*)&Bs[cur][kk][tx * 8 + 4];
            float ra[8] = {a0.x, a0.y, a0.z, a0.w, a1.x, a1.y, a1.z, a1.w};
            float rb[8] = {b0.x, b0.y, b0.z, b0.w, b1.x, b1.y, b1.z, b1.w};
#pragma unroll
            for (int i = 0; i < 8; i++)
#pragma unroll
                for (int j = 0; j < 8; j++) acc[i][j] = fmaf(ra[i], rb[j], acc[i][j]);
        }
        if (t + 1 < nt) {
            int nxt = cur ^ 1;
#pragma unroll
            for (int i = 0; i < 8; i++) { As[nxt][ac[i]][ar[i]] = ldA[i]; Bs[nxt][br[i]][bc[i]] = ldB[i]; }
            __syncthreads();
            cur = nxt;
        }
    }
    float thr = (EPI == 2) ? thr_p[0] : 0.f;
#pragma unroll
    for (int i = 0; i < 8; i++) {
        int gr = row0 + ty * 8 + i;
        if (gr >= M) continue;
#pragma unroll
        for (int j = 0; j < 8; j++) {
            int gc = col0 + tx * 8 + j;
            if (gc >= N) continue;
            float v = acc[i][j] + (bias ? bias[gc] : 0.f);
            if (EPI == 1) v = fmaxf(v, 0.f);
            if (EPI == 2) { v = fmaxf(v, 0.f); v = fmaxf(v - thr, 0.f); }
            C[(long)gr * N + gc] = v;
        }
    }
}

// ---------------- GCN gather: fp32 in (hw), fp16 out (next GEMM A) ---------
__global__ void k_gather(const float* __restrict__ hw, const float* __restrict__ bias,
                         __half* __restrict__ out, int F)
{
    int n = blockIdx.x * 4 + threadIdx.y;
    if (n >= NN) return;
    int f4 = threadIdx.x;
    int Fq = F >> 2;
    const float4* __restrict__ hw4 = (const float4*)hw;
    float d = g_dinv[n];
    float c = d * d;
    float4 sv = hw4[(long)n * Fq + f4];
    float ax = sv.x * c, ay = sv.y * c, az = sv.z * c, aw = sv.w * c;
    int s = g_rowptr[n], e = g_rowptr[n + 1];
    int i = s;
    for (; i + 4 <= e; i += 4) {
        int   c0 = g_col[i],  c1 = g_col[i + 1], c2 = g_col[i + 2], c3 = g_col[i + 3];
        float w0 = g_wgt[i],  w1 = g_wgt[i + 1], w2 = g_wgt[i + 2], w3 = g_wgt[i + 3];
        float4 v0 = hw4[(long)c0 * Fq + f4];
        float4 v1 = hw4[(long)c1 * Fq + f4];
        float4 v2 = hw4[(long)c2 * Fq + f4];
        float4 v3 = hw4[(long)c3 * Fq + f4];
        ax += w0 * v0.x + w1 * v1.x + w2 * v2.x + w3 * v3.x;
        ay += w0 * v0.y + w1 * v1.y + w2 * v2.y + w3 * v3.y;
        az += w0 * v0.z + w1 * v1.z + w2 * v2.z + w3 * v3.z;
        aw += w0 * v0.w + w1 * v1.w + w2 * v2.w + w3 * v3.w;
    }
    for (; i < e; i++) {
        int c0 = g_col[i]; float w0 = g_wgt[i];
        float4 v0 = hw4[(long)c0 * Fq + f4];
        ax += w0 * v0.x; ay += w0 * v0.y; az += w0 * v0.z; aw += w0 * v0.w;
    }
    float4 b = ((const float4*)bias)[f4];
    ax += b.x; ay += b.y; az += b.z; aw += b.w;
    ax = ax > 0.f ? ax : expm1f(ax);
    ay = ay > 0.f ? ay : expm1f(ay);
    az = az > 0.f ? az : expm1f(az);
    aw = aw > 0.f ? aw : expm1f(aw);
    __half2 h01 = __floats2half2_rn(ax, ay);
    __half2 h23 = __floats2half2_rn(az, aw);
    __half2* o2 = (__half2*)(out + (long)n * F + f4 * 4);
    o2[0] = h01; o2[1] = h23;
}

// ---------------- pair readout: fp16 in/out ----------------
__global__ void k_pair(const __half* __restrict__ h,
                       const int* __restrict__ i1, const int* __restrict__ i2,
                       __half* __restrict__ xc)
{
    int p = blockIdx.x;
    int f = threadIdx.x;
    float v = (f < 128) ? __half2float(h[(long)i1[p] * 128 + f])
                        : __half2float(h[(long)i2[p] * 128 + (f - 128)]);
    __shared__ float red[256];
    red[f] = v * v;
    __syncthreads();
    for (int off = 128; off > 0; off >>= 1) {
        if (f < off) red[f] += red[f + off];
        __syncthreads();
    }
    float norm = fmaxf(sqrtf(red[0]), 1e-12f);
    xc[(long)p * 256 + f] = __float2half_rn(v / norm);
}

__global__ void k_out(const float* __restrict__ x, const float* __restrict__ W,
                      const float* __restrict__ b, float* __restrict__ out)
{
    int idx = blockIdx.x * blockDim.x + threadIdx.x;
    if (idx >= NB * 2) return;
    int p = idx >> 1, c = idx & 1;
    float acc = b[c];
#pragma unroll
    for (int k = 0; k < 64; k++) acc += x[p * 64 + k] * W[k * 2 + c];
    out[idx] = acc;
}

// ---------------- launch ----------------
extern "C" void kernel_launch(void* const* d_in, const int* in_sizes, int n_in,
                              void* d_out, int out_size)
{
    const float* cid   = (const float*)d_in[0];
    const int*   edges = (const int*)  d_in[1];
    const int*   i1    = (const int*)  d_in[2];
    const int*   i2    = (const int*)  d_in[3];
    const float* thr   = (const float*)d_in[4];
    const float* bb2W  = (const float*)d_in[5];  const float* bb2b = (const float*)d_in[6];
    const float* bb3W  = (const float*)d_in[7];  const float* bb3b = (const float*)d_in[8];
    const float* g1W   = (const float*)d_in[9];  const float* g1b  = (const float*)d_in[10];
    const float* g2W   = (const float*)d_in[11]; const float* g2b  = (const float*)d_in[12];
    const float* g3W   = (const float*)d_in[13]; const float* g3b  = (const float*)d_in[14];
    const float* g4W   = (const float*)d_in[15]; const float* g4b  = (const float*)d_in[16];
    const float* g5W   = (const float*)d_in[17]; const float* g5b  = (const float*)d_in[18];
    const float* f1W   = (const float*)d_in[19]; const float* f1b  = (const float*)d_in[20];
    const float* f2W   = (const float*)d_in[21]; const float* f2b  = (const float*)d_in[22];
    const float* f3W   = (const float*)d_in[23]; const float* f3b  = (const float*)d_in[24];
    const float* oW    = (const float*)d_in[25]; const float* ob   = (const float*)d_in[26];

    void *pcid, *px1, *px, *ph, *phw, *ppc, *pf1, *pf2, *pf3, *pwt;
    cudaGetSymbolAddress(&pcid, g_cid);
    cudaGetSymbolAddress(&px1,  g_x1);
    cudaGetSymbolAddress(&px,   g_x);
    cudaGetSymbolAddress(&ph,   g_h);
    cudaGetSymbolAddress(&phw,  g_hw);
    cudaGetSymbolAddress(&ppc,  g_pc);
    cudaGetSymbolAddress(&pf1,  g_f1);
    cudaGetSymbolAddress(&pf2,  g_f2);
    cudaGetSymbolAddress(&pf3,  g_f3);
    cudaGetSymbolAddress(&pwt,  g_wt);
    __half* cidp = (__half*)pcid;
    __half* x1   = (__half*)px1;
    __half* x    = (__half*)px;
    __half* h    = (__half*)ph;
    float*  hw   = (float*)phw;
    __half* pc   = (__half*)ppc;
    __half* f1o  = (__half*)pf1;
    float*  f2o  = (float*)pf2;
    float*  f3o  = (float*)pf3;
    __half* wt   = (__half*)pwt;

    // graph preprocessing
    k_zero_deg<<<(NN + 255) / 256, 256>>>();
    k_count<<<(NE + 255) / 256, 256>>>(edges);
    k_dinv<<<(NN + 255) / 256, 256>>>();
    k_scanA<<<NSB, 256>>>();
    k_scanB<<<1, 128>>>();
    k_scanC<<<NSB, 256>>>();
    k_fill<<<(NE + 255) / 256, 256>>>(edges);

    // producers: fp16 padded input + transposed fp16 weights
    k_pad_cid<<<(NNP * 896 + 255) / 256, 256>>>(cid);
    k_zero_wt<<<(WT_ZERO + 255) / 256, 256>>>();
    dim3 tb(32, 8);
    k_transpose2<<<dim3(28, 28), tb>>>(bb2W, wt + OFF_BB2, 881, 881, 896);
    k_transpose2<<<dim3(8, 28),  tb>>>(bb3W, wt + OFF_BB3, 881, 256, 896);
    k_transpose2<<<dim3(8, 8),   tb>>>(g1W,  wt + OFF_G1,  256, 256, 256);
    k_transpose2<<<dim3(8, 8),   tb>>>(g2W,  wt + OFF_G2,  256, 256, 256);
    k_transpose2<<<dim3(8, 8),   tb>>>(g3W,  wt + OFF_G3,  256, 256, 256);
    k_transpose2<<<dim3(4, 8),   tb>>>(g4W,  wt + OFF_G4,  256, 128, 256);
    k_transpose2<<<dim3(4, 4),   tb>>>(g5W,  wt + OFF_G5,  128, 128, 128);
    k_transpose2<<<dim3(32, 8),  tb>>>(f1W,  wt + OFF_F1,  256, 1024, 256);
    k_transpose2<<<dim3(8, 32),  tb>>>(f2W,  wt + OFF_F2,  1024, 256, 1024);

    int MY = NNP / 128;  // 235

    // BasicBlock
    k_hgemm<2,1><<<dim3(7, MY), 256>>>(cidp, wt + OFF_BB2, bb2b, thr, x1,
                                       NN, 881, 896, 896, 896, 896, 896);
    k_hgemm<1,1><<<dim3(2, MY), 256>>>(x1, wt + OFF_BB3, bb3b, nullptr, x,
                                       NN, 256, 896, 896, 896, 256, 256);

    // GCN layers
    dim3 gat256(64, 4), gat128(32, 4);
    int  ngb = (NN + 3) / 4;
    k_hgemm<0,0><<<dim3(2, MY), 256>>>(x, wt + OFF_G1, nullptr, nullptr, hw,
                                       NN, 256, 256, 256, 256, 256, 256);
    k_gather<<<ngb, gat256>>>(hw, g1b, h, 256);
    k_hgemm<0,0><<<dim3(2, MY), 256>>>(h, wt + OFF_G2, nullptr, nullptr, hw,
                                       NN, 256, 256, 256, 256, 256, 256);
    k_gather<<<ngb, gat256>>>(hw, g2b, x, 256);
    k_hgemm<0,0><<<dim3(2, MY), 256>>>(x, wt + OFF_G3, nullptr, nullptr, hw,
                                       NN, 256, 256, 256, 256, 256, 256);
    k_gather<<<ngb, gat256>>>(hw, g3b, h, 256);
    k_hgemm<0,0><<<dim3(1, MY), 256>>>(h, wt + OFF_G4, nullptr, nullptr, hw,
                                       NN, 128, 256, 256, 256, 128, 128);
    k_gather<<<ngb, gat128>>>(hw, g4b, x, 128);
    k_hgemm<0,0><<<dim3(1, MY), 256>>>(x, wt + OFF_G5, nullptr, nullptr, hw,
                                       NN, 128, 128, 128, 128, 128, 128);
    k_gather<<<ngb, gat128>>>(hw, g5b, h, 128);

    // pair readout
    k_pair<<<NB, 256>>>(h, i1, i2, pc);
    k_hgemm<1,1><<<dim3(8, 32), 256>>>(pc,  wt + OFF_F1, f1b, nullptr, f1o,
                                       NB, 1024, 256, 256, 256, 1024, 1024);
    k_hgemm<1,0><<<dim3(2, 32), 256>>>(f1o, wt + OFF_F2, f2b, nullptr, f2o,
                                       NB, 256, 1024, 1024, 1024, 256, 256);
    k_sgemm<1><<<dim3(1, 32), 256>>>(f2o, f3W, f3b, nullptr, f3o, NB, 64, 256);
    k_out<<<(NB * 2 + 255) / 256, 256>>>(f3o, oW, ob, (float*)d_out);
}